// round 3
// baseline (speedup 1.0000x reference)
#include <cuda_runtime.h>
#include <math.h>

// Problem constants (from reference)
#define MAXN   524288
#define SPIN   1000
#define TRAINN 400000
#define ML_C   2.9086f
#define SL_C   1.898f

#define TILE   2048
#define SEQ_THREADS 128

// Scratch (no allocations allowed)
__device__ float  g_ol[MAXN];    // precomputed ol gate (depends only on u2)
__device__ float  g_c[MAXN];     // state entering each step
__device__ double g_acc[2];      // sum, sumsq for obsstd
__device__ float  g_par[12];
// g_par: 0=A2 1=B2 (exp2 coeffs for oo-sigmoid: exp(-z)=exp2(A2*c0+B2))
//        2=oo1 3=ol1 4=svm 5=thr 6=K(=thr*500) 7=AL 8=BL (ol-sigmoid coeffs)
//        9=obsstd

// ---------------------------------------------------------------------------
__global__ void k_setup(const float* pm, const float* ps,
                        const float* wr_yom, const float* wr_ylm,
                        const float* wr_yfm, const float* wr_yvm,
                        const float* b0_yom, const float* wb1p,
                        const float* b0_ylm, const float* wb2p,
                        const float* b0_yrm) {
    const float LOG2E = 1.4426950408889634f;
    float mo = pm[0], so = ps[0];
    float wb1 = wb1p[0], wb2 = wb2p[0];
    float eo = expf(wr_yom[0]);
    float el = expf(wr_ylm[0]);
    float ef = expf(wr_yfm[0]);
    float den = eo + el + ef;
    float oo1 = eo / den;
    float ol1 = el / den;
    float svm = 1.0f / (1.0f + expf(-wr_yvm[0]));
    float thr = expf(b0_yrm[0]);

    float a = wb1 / so;           // z_oo = b0_yom + (c0 - mo)*a
    g_par[0] = -LOG2E * a;
    g_par[1] = -LOG2E * (b0_yom[0] - mo * a);
    g_par[2] = oo1;
    g_par[3] = ol1;
    g_par[4] = svm;
    g_par[5] = thr;
    g_par[6] = thr * 500.0f;
    float al = wb2 / SL_C;        // z_ol = b0_ylm + (u2 - ML)*al
    g_par[7] = -LOG2E * al;
    g_par[8] = -LOG2E * (b0_ylm[0] - ML_C * al);
    g_acc[0] = 0.0;
    g_acc[1] = 0.0;
}

// ---------------------------------------------------------------------------
// Precompute ol[i] = ol1 * sigmoid(b0_ylm + (u2-ML)/SL*wb2)  (input-only gate)
__global__ void k_prepass(const float2* __restrict__ x, int n) {
    int i = blockIdx.x * blockDim.x + threadIdx.x;
    if (i >= n) return;
    float u2 = x[i].y;
    float t = fmaf(u2, g_par[7], g_par[8]);
    float e;
    asm("ex2.approx.f32 %0, %1;" : "=f"(e) : "f"(t));
    g_ol[i] = g_par[3] / (1.0f + e);
}

// ---------------------------------------------------------------------------
// obsstd reduction over y_obs[SPIN:TRAINN], double accumulation
__global__ void k_reduce(const float* __restrict__ y, int ny) {
    int hi = TRAINN < ny ? TRAINN : ny;
    int count = hi - SPIN;
    double s = 0.0, s2 = 0.0;
    for (int i = blockIdx.x * blockDim.x + threadIdx.x; i < count;
         i += gridDim.x * blockDim.x) {
        double v = (double)y[SPIN + i];
        s  += v;
        s2 += v * v;
    }
    #pragma unroll
    for (int o = 16; o; o >>= 1) {
        s  += __shfl_down_sync(0xFFFFFFFFu, s,  o);
        s2 += __shfl_down_sync(0xFFFFFFFFu, s2, o);
    }
    if ((threadIdx.x & 31) == 0) {
        atomicAdd(&g_acc[0], s);
        atomicAdd(&g_acc[1], s2);
    }
}

__global__ void k_finalize(int ny) {
    int hi = TRAINN < ny ? TRAINN : ny;
    double cnt = (double)(hi - SPIN);
    double var = (g_acc[1] - g_acc[0] * g_acc[0] / cnt) / (cnt - 1.0);
    g_par[9] = (float)sqrt(var > 0.0 ? var : 0.0);
}

// ---------------------------------------------------------------------------
// The sequential recurrence. One block; threads stage tiles into smem,
// lane 0 runs the scalar recurrence. Inner loop is fully branch-free:
// time_lag is hoisted (state provably stays 0 for i < tl), and the affine-in-r
// restructure turns (f,ov,min) into max of two FFMAs off the rcp result.
__global__ void __launch_bounds__(SEQ_THREADS, 1)
k_scan(const float2* __restrict__ x, int n, const int* __restrict__ tlp) {
    __shared__ float su1[TILE], su2[TILE], sol[TILE], sc[TILE];
    int tl = tlp[0];
    if (tl < 0) tl = 0;
    if (tl > n) tl = n;

    // Prefix: state entering every step i < tl is exactly 0.
    for (int i = threadIdx.x; i < tl; i += SEQ_THREADS) g_c[i] = 0.0f;

    float A2  = g_par[0], B2 = g_par[1], oo1 = g_par[2];
    float svm = g_par[4], thr = g_par[5], K = g_par[6];
    float c = 0.0f;

    for (int base = tl; base < n; base += TILE) {
        int lim = n - base; if (lim > TILE) lim = TILE;
        for (int j = threadIdx.x; j < lim; j += SEQ_THREADS) {
            float2 xv = x[base + j];
            su1[j] = xv.x;
            su2[j] = xv.y;
            sol[j] = g_ol[base + j];
        }
        __syncthreads();
        if (threadIdx.x == 0) {
            float cl = c;
            #pragma unroll 8
            for (int j = 0; j < lim; j++) {
                float c0 = cl;
                sc[j] = c0;                       // state ENTERING this step
                float u1 = su1[j], u2 = su2[j], ol = sol[j];

                // --- critical chain: c0 -> t -> e -> d -> r -> a1/a2 -> max
                float t = fmaf(c0, A2, B2);       // exp(-z) = 2^t
                float e;  asm("ex2.approx.f32 %0, %1;" : "=f"(e) : "f"(t));
                float d = 1.0f + e;
                float r;  asm("rcp.approx.f32 %0, %1;" : "=f"(r) : "f"(d));

                // --- off-chain work (hidden under ex2/rcp latency)
                float rc; asm("rcp.approx.f32 %0, %1;" : "=f"(rc) : "f"(c0));
                float q   = u2 * rc;
                float m   = fminf(ol, q);         // NaN-safe: returns ol if q is NaN
                float olc = (c0 > 0.0f) ? m : ol;
                float om  = 1.0f - olc;           // 1 - olc
                float Bv  = fmaf(om, c0, u1);     // (1-olc)*c0 + u1
                float s   = fmaf(c0, 0.002f, -thr);
                float sg  = (s > 0.0f) ? svm : ((s < 0.0f) ? -svm : 0.0f);
                float absd = fabsf(c0 - K);
                float B1  = fmaf(-sg, absd, Bv);  // Bv - sg*absd
                float B2a = fmaf(-om, absd, Bv);  // Bv - om*absd
                float k1  = -oo1 * c0;
                float k2  = oo1 * (absd - c0);

                // cl = (f*c0+u1) - min(sg,f)*absd  ==  max of two affines in r
                float a1 = fmaf(k1, r, B1);
                float a2 = fmaf(k2, r, B2a);
                cl = fmaxf(a1, a2);
            }
            c = cl;
        }
        __syncthreads();
        for (int j = threadIdx.x; j < lim; j += SEQ_THREADS)
            g_c[base + j] = sc[j];
        __syncthreads();
    }
}

// ---------------------------------------------------------------------------
// Parallel epilogue: recompute gates from the state trajectory, write all
// 14 output columns.
// Layout: [h_n | c_n | l_n | lc_n | z | z | Goo | Gol | Golc | Gf |
//          h_nout(N,2 interleaved) | obs_std | Gov]
__global__ void k_out(const float2* __restrict__ x, int n,
                      const int* __restrict__ tlp, float* __restrict__ out) {
    int i = blockIdx.x * blockDim.x + threadIdx.x;
    if (i >= n) return;
    int tl = tlp[0];
    long long nn = n;
    if (i < tl) {
        out[i] = 0.0f;            out[nn + i] = 0.0f;
        out[2*nn + i] = 0.0f;     out[3*nn + i] = 0.0f;
        out[4*nn + i] = 0.0f;     out[5*nn + i] = 0.0f;
        out[6*nn + i] = 0.0f;     out[7*nn + i] = 0.0f;
        out[8*nn + i] = 0.0f;     out[9*nn + i] = 0.0f;
        out[10*nn + 2*(long long)i]     = 0.0f;
        out[10*nn + 2*(long long)i + 1] = 0.0f;
        out[12*nn + i] = 0.0f;    out[13*nn + i] = 0.0f;
        return;
    }
    float c0 = g_c[i];
    float u2 = x[i].y;
    float ol = g_ol[i];
    float thr = g_par[5], svm = g_par[4];

    float t = fmaf(c0, g_par[0], g_par[1]);
    float e;  asm("ex2.approx.f32 %0, %1;" : "=f"(e) : "f"(t));
    float oo = g_par[2] / (1.0f + e);
    float olc;
    if (c0 > 0.0f) olc = fminf(ol, u2 / c0); else olc = ol;
    float f = (1.0f - oo) - olc;
    float s = fmaf(c0, 0.002f, -thr);
    float sg = (s > 0.0f) ? svm : ((s < 0.0f) ? -svm : 0.0f);
    float ov = fminf(sg, f);
    float obss = g_par[9];
    float h = oo * c0;

    out[i]         = h;
    out[nn + i]    = c0;
    out[2*nn + i]  = ol * c0;
    out[3*nn + i]  = olc * c0;
    out[4*nn + i]  = 0.0f;
    out[5*nn + i]  = 0.0f;
    out[6*nn + i]  = oo;
    out[7*nn + i]  = ol;
    out[8*nn + i]  = olc;
    out[9*nn + i]  = f;
    out[10*nn + 2*(long long)i]     = h;
    out[10*nn + 2*(long long)i + 1] = obss;
    out[12*nn + i] = obss;
    out[13*nn + i] = ov;
}

// ---------------------------------------------------------------------------
extern "C" void kernel_launch(void* const* d_in, const int* in_sizes, int n_in,
                              void* d_out, int out_size) {
    const float2* x   = (const float2*)d_in[0];
    const float*  y   = (const float*)d_in[1];
    const float*  pm  = (const float*)d_in[2];
    const float*  ps  = (const float*)d_in[3];
    const float*  wr_yom = (const float*)d_in[4];
    const float*  wr_ylm = (const float*)d_in[5];
    const float*  wr_yfm = (const float*)d_in[6];
    const float*  wr_yvm = (const float*)d_in[7];
    const float*  b0_yom = (const float*)d_in[8];
    const float*  wb1    = (const float*)d_in[9];
    const float*  b0_ylm = (const float*)d_in[10];
    const float*  wb2    = (const float*)d_in[11];
    const float*  b0_yrm = (const float*)d_in[12];
    const int*    tlp    = (const int*)d_in[14];   // time_lag
    float* out = (float*)d_out;
    (void)n_in; (void)out_size;

    int n  = in_sizes[0] / 2;
    if (n > MAXN) n = MAXN;
    int ny = in_sizes[1];

    k_setup<<<1, 1>>>(pm, ps, wr_yom, wr_ylm, wr_yfm, wr_yvm,
                      b0_yom, wb1, b0_ylm, wb2, b0_yrm);
    k_prepass<<<(n + 255) / 256, 256>>>(x, n);
    k_reduce<<<160, 256>>>(y, ny);
    k_finalize<<<1, 1>>>(ny);
    k_scan<<<1, SEQ_THREADS>>>(x, n, tlp);
    k_out<<<(n + 255) / 256, 256>>>(x, n, tlp, out);
}

// round 4
// speedup vs baseline: 1.5982x; 1.5982x over previous
#include <cuda_runtime.h>
#include <math.h>

// Problem constants (from reference)
#define MAXN   524288
#define SPIN   1000
#define TRAINN 400000
#define ML_C   2.9086f
#define SL_C   1.898f

#define TILE   2048
#define SEQ_THREADS 128

// Scratch (no allocations allowed)
__device__ float  g_ol[MAXN];    // precomputed ol gate (depends only on u2)
__device__ float  g_c[MAXN];     // state entering each step
__device__ double g_acc[2];      // sum, sumsq for obsstd
__device__ float  g_par[12];
// g_par: 0=A2 1=B2 (exp2 coeffs: exp(-z_oo)=exp2(A2*c0+B2))
//        2=oo1 3=ol1 4=svm 5=thr 6=K(=thr*500) 7=AL 8=BL 9=obsstd

// ---------------------------------------------------------------------------
__global__ void k_setup(const float* pm, const float* ps,
                        const float* wr_yom, const float* wr_ylm,
                        const float* wr_yfm, const float* wr_yvm,
                        const float* b0_yom, const float* wb1p,
                        const float* b0_ylm, const float* wb2p,
                        const float* b0_yrm) {
    const float LOG2E = 1.4426950408889634f;
    float mo = pm[0], so = ps[0];
    float wb1 = wb1p[0], wb2 = wb2p[0];
    float eo = expf(wr_yom[0]);
    float el = expf(wr_ylm[0]);
    float ef = expf(wr_yfm[0]);
    float den = eo + el + ef;
    float oo1 = eo / den;
    float ol1 = el / den;
    float svm = 1.0f / (1.0f + expf(-wr_yvm[0]));
    float thr = expf(b0_yrm[0]);

    float a = wb1 / so;           // z_oo = b0_yom + (c0 - mo)*a
    g_par[0] = -LOG2E * a;
    g_par[1] = -LOG2E * (b0_yom[0] - mo * a);
    g_par[2] = oo1;
    g_par[3] = ol1;
    g_par[4] = svm;
    g_par[5] = thr;
    g_par[6] = thr * 500.0f;
    float al = wb2 / SL_C;        // z_ol = b0_ylm + (u2 - ML)*al
    g_par[7] = -LOG2E * al;
    g_par[8] = -LOG2E * (b0_ylm[0] - ML_C * al);
    g_acc[0] = 0.0;
    g_acc[1] = 0.0;
}

// ---------------------------------------------------------------------------
// Precompute ol[i] = ol1 * sigmoid(b0_ylm + (u2-ML)/SL*wb2)  (input-only gate)
__global__ void k_prepass(const float2* __restrict__ x, int n) {
    int i = blockIdx.x * blockDim.x + threadIdx.x;
    if (i >= n) return;
    float u2 = x[i].y;
    float t = fmaf(u2, g_par[7], g_par[8]);
    float e;
    asm("ex2.approx.f32 %0, %1;" : "=f"(e) : "f"(t));
    g_ol[i] = g_par[3] / (1.0f + e);
}

// ---------------------------------------------------------------------------
__global__ void k_reduce(const float* __restrict__ y, int ny) {
    int hi = TRAINN < ny ? TRAINN : ny;
    int count = hi - SPIN;
    double s = 0.0, s2 = 0.0;
    for (int i = blockIdx.x * blockDim.x + threadIdx.x; i < count;
         i += gridDim.x * blockDim.x) {
        double v = (double)y[SPIN + i];
        s  += v;
        s2 += v * v;
    }
    #pragma unroll
    for (int o = 16; o; o >>= 1) {
        s  += __shfl_down_sync(0xFFFFFFFFu, s,  o);
        s2 += __shfl_down_sync(0xFFFFFFFFu, s2, o);
    }
    if ((threadIdx.x & 31) == 0) {
        atomicAdd(&g_acc[0], s);
        atomicAdd(&g_acc[1], s2);
    }
}

__global__ void k_finalize(int ny) {
    int hi = TRAINN < ny ? TRAINN : ny;
    double cnt = (double)(hi - SPIN);
    double var = (g_acc[1] - g_acc[0] * g_acc[0] / cnt) / (cnt - 1.0);
    g_par[9] = (float)sqrt(var > 0.0 ? var : 0.0);
}

// ---------------------------------------------------------------------------
// Sequential recurrence, double-buffered. Thread 0 computes tile k while
// threads 1..127 prefetch tile k+1 and drain tile k-1's state trajectory.
//
// Per-step math (branch-free, all selects 2-way FSEL):
//   cl = max( fma(-oo1*c0, r, Bv - sg*absd),
//             fma( oo1*(absd-c0), r, (Bv - absd) + oab) )
//   r   = rcp(1 + exp2(A2*c0 + B2))            (the oo-sigmoid)
//   Bv  = c0 + u1 - mlc,  mlc = olc*c0 = sel(min(ol*c0, u2), ol*c0)
//   oab = olc*absd        = sel(min(ol*absd, u2*absd*rcp(c0)), ol*absd)
__global__ void __launch_bounds__(SEQ_THREADS, 1)
k_scan(const float2* __restrict__ x, int n, const int* __restrict__ tlp) {
    __shared__ float4 sin_[2][TILE];   // (u1, u2, ol, -)
    __shared__ float  ssc[2][TILE];    // state entering each step

    int tl = tlp[0];
    if (tl < 0) tl = 0;
    if (tl > n) tl = n;

    // Prefix: state entering every step i < tl is exactly 0.
    for (int i = threadIdx.x; i < tl; i += SEQ_THREADS) g_c[i] = 0.0f;

    int nrem = n - tl;
    if (nrem <= 0) return;
    int ntiles = (nrem + TILE - 1) / TILE;

    float A2  = g_par[0], B2 = g_par[1], oo1 = g_par[2];
    float svm = g_par[4], thr = g_par[5], K = g_par[6];
    float noo1 = -oo1, nsvm = -svm, mthr = -thr;

    // Preload tile 0 (all threads)
    {
        int lim0 = nrem < TILE ? nrem : TILE;
        for (int j = threadIdx.x; j < lim0; j += SEQ_THREADS) {
            float2 xv = x[tl + j];
            sin_[0][j] = make_float4(xv.x, xv.y, g_ol[tl + j], 0.0f);
        }
    }
    __syncthreads();

    float c = 0.0f;
    for (int k = 0; k < ntiles; k++) {
        int buf  = k & 1;
        int base = tl + k * TILE;
        int lim  = n - base; if (lim > TILE) lim = TILE;

        if (threadIdx.x == 0) {
            float cl = c;
            #pragma unroll 4
            for (int j = 0; j < lim; j++) {
                float4 v = sin_[buf][j];          // u1=v.x u2=v.y ol=v.z
                float c0 = cl;
                ssc[buf][j] = c0;

                // critical chain: c0 -> t -> e -> d -> r
                float t = fmaf(c0, A2, B2);
                float e;  asm("ex2.approx.f32 %0, %1;" : "=f"(e) : "f"(t));
                float d = 1.0f + e;
                float r;  asm("rcp.approx.f32 %0, %1;" : "=f"(r) : "f"(d));
                float rc; asm("rcp.approx.f32 %0, %1;" : "=f"(rc) : "f"(c0));

                bool  pos  = c0 > 0.0f;
                float absd = fabsf(c0 - K);
                float olc0 = v.z * c0;
                float mn   = fminf(olc0, v.y);
                float mlc  = pos ? mn : olc0;              // olc*c0
                float Bv   = (c0 + v.x) - mlc;

                float s   = fmaf(c0, 0.002f, mthr);
                float sgp = (s > 0.0f) ? svm : 0.0f;       // flat FSELs
                float sg  = (s < 0.0f) ? nsvm : sgp;
                float C1  = fmaf(-sg, absd, Bv);
                float k1  = noo1 * c0;

                float qa   = v.y * absd;
                float qr   = qa * rc;
                float ola  = v.z * absd;
                float oabm = fminf(ola, qr);
                float oab  = pos ? oabm : ola;             // olc*absd
                float k2   = oo1 * (absd - c0);
                float C2   = (Bv - absd) + oab;

                float a1 = fmaf(k1, r, C1);
                float a2 = fmaf(k2, r, C2);
                cl = fmaxf(a1, a2);
            }
            c = cl;
        } else {
            // Prefetch tile k+1
            int nbase = base + TILE;
            if (nbase < n) {
                int nlim = n - nbase; if (nlim > TILE) nlim = TILE;
                for (int j = threadIdx.x - 1; j < nlim; j += (SEQ_THREADS - 1)) {
                    float2 xv = x[nbase + j];
                    sin_[buf ^ 1][j] = make_float4(xv.x, xv.y, g_ol[nbase + j], 0.0f);
                }
            }
            // Drain tile k-1 (always full TILE: only the last tile is partial)
            if (k > 0) {
                int pbase = base - TILE;
                for (int j = threadIdx.x - 1; j < TILE; j += (SEQ_THREADS - 1))
                    g_c[pbase + j] = ssc[buf ^ 1][j];
            }
        }
        __syncthreads();
    }

    // Drain the final tile
    {
        int base = tl + (ntiles - 1) * TILE;
        int lim  = n - base; if (lim > TILE) lim = TILE;
        for (int j = threadIdx.x; j < lim; j += SEQ_THREADS)
            g_c[base + j] = ssc[(ntiles - 1) & 1][j];
    }
}

// ---------------------------------------------------------------------------
// Parallel epilogue: recompute gates from the state trajectory.
// Layout: [h_n | c_n | l_n | lc_n | z | z | Goo | Gol | Golc | Gf |
//          h_nout(N,2 interleaved) | obs_std | Gov]
__global__ void k_out(const float2* __restrict__ x, int n,
                      const int* __restrict__ tlp, float* __restrict__ out) {
    int i = blockIdx.x * blockDim.x + threadIdx.x;
    if (i >= n) return;
    int tl = tlp[0];
    long long nn = n;
    if (i < tl) {
        out[i] = 0.0f;            out[nn + i] = 0.0f;
        out[2*nn + i] = 0.0f;     out[3*nn + i] = 0.0f;
        out[4*nn + i] = 0.0f;     out[5*nn + i] = 0.0f;
        out[6*nn + i] = 0.0f;     out[7*nn + i] = 0.0f;
        out[8*nn + i] = 0.0f;     out[9*nn + i] = 0.0f;
        out[10*nn + 2*(long long)i]     = 0.0f;
        out[10*nn + 2*(long long)i + 1] = 0.0f;
        out[12*nn + i] = 0.0f;    out[13*nn + i] = 0.0f;
        return;
    }
    float c0 = g_c[i];
    float u2 = x[i].y;
    float ol = g_ol[i];
    float thr = g_par[5], svm = g_par[4];

    float t = fmaf(c0, g_par[0], g_par[1]);
    float e;  asm("ex2.approx.f32 %0, %1;" : "=f"(e) : "f"(t));
    float oo = g_par[2] / (1.0f + e);
    float olc;
    if (c0 > 0.0f) olc = fminf(ol, u2 / c0); else olc = ol;
    float f = (1.0f - oo) - olc;
    float s = fmaf(c0, 0.002f, -thr);
    float sg = (s > 0.0f) ? svm : ((s < 0.0f) ? -svm : 0.0f);
    float ov = fminf(sg, f);
    float obss = g_par[9];
    float h = oo * c0;

    out[i]         = h;
    out[nn + i]    = c0;
    out[2*nn + i]  = ol * c0;
    out[3*nn + i]  = olc * c0;
    out[4*nn + i]  = 0.0f;
    out[5*nn + i]  = 0.0f;
    out[6*nn + i]  = oo;
    out[7*nn + i]  = ol;
    out[8*nn + i]  = olc;
    out[9*nn + i]  = f;
    out[10*nn + 2*(long long)i]     = h;
    out[10*nn + 2*(long long)i + 1] = obss;
    out[12*nn + i] = obss;
    out[13*nn + i] = ov;
}

// ---------------------------------------------------------------------------
extern "C" void kernel_launch(void* const* d_in, const int* in_sizes, int n_in,
                              void* d_out, int out_size) {
    const float2* x   = (const float2*)d_in[0];
    const float*  y   = (const float*)d_in[1];
    const float*  pm  = (const float*)d_in[2];
    const float*  ps  = (const float*)d_in[3];
    const float*  wr_yom = (const float*)d_in[4];
    const float*  wr_ylm = (const float*)d_in[5];
    const float*  wr_yfm = (const float*)d_in[6];
    const float*  wr_yvm = (const float*)d_in[7];
    const float*  b0_yom = (const float*)d_in[8];
    const float*  wb1    = (const float*)d_in[9];
    const float*  b0_ylm = (const float*)d_in[10];
    const float*  wb2    = (const float*)d_in[11];
    const float*  b0_yrm = (const float*)d_in[12];
    const int*    tlp    = (const int*)d_in[14];   // time_lag
    float* out = (float*)d_out;
    (void)n_in; (void)out_size;

    int n  = in_sizes[0] / 2;
    if (n > MAXN) n = MAXN;
    int ny = in_sizes[1];

    k_setup<<<1, 1>>>(pm, ps, wr_yom, wr_ylm, wr_yfm, wr_yvm,
                      b0_yom, wb1, b0_ylm, wb2, b0_yrm);
    k_prepass<<<(n + 255) / 256, 256>>>(x, n);
    k_reduce<<<160, 256>>>(y, ny);
    k_finalize<<<1, 1>>>(ny);
    k_scan<<<1, SEQ_THREADS>>>(x, n, tlp);
    k_out<<<(n + 255) / 256, 256>>>(x, n, tlp, out);
}

// round 5
// speedup vs baseline: 98.0992x; 61.3792x over previous
#include <cuda_runtime.h>
#include <math.h>

// Problem constants (from reference)
#define MAXN   524288
#define SPIN   1000
#define TRAINN 400000
#define ML_C   2.9086f
#define SL_C   1.898f

#define TILE   2048
#define SEQ_THREADS 128
#define CHUNKS 128        // parallel speculative chunks
#define WARM   4096       // warm-up steps per chunk (contraction burn-in)

// Scratch (no allocations allowed)
__device__ float  g_ol[MAXN];    // precomputed ol gate (depends only on u2)
__device__ float  g_c[MAXN];     // state entering each step
__device__ double g_acc[2];      // sum, sumsq for obsstd
__device__ float  g_par[12];
// g_par: 0=A2 1=B2 (exp2 coeffs: exp(-z_oo)=exp2(A2*c0+B2))
//        2=oo1 3=ol1 4=svm 5=thr 6=K(=thr*500) 7=AL 8=BL 9=obsstd

// ---------------------------------------------------------------------------
__global__ void k_setup(const float* pm, const float* ps,
                        const float* wr_yom, const float* wr_ylm,
                        const float* wr_yfm, const float* wr_yvm,
                        const float* b0_yom, const float* wb1p,
                        const float* b0_ylm, const float* wb2p,
                        const float* b0_yrm) {
    const float LOG2E = 1.4426950408889634f;
    float mo = pm[0], so = ps[0];
    float wb1 = wb1p[0], wb2 = wb2p[0];
    float eo = expf(wr_yom[0]);
    float el = expf(wr_ylm[0]);
    float ef = expf(wr_yfm[0]);
    float den = eo + el + ef;
    float oo1 = eo / den;
    float ol1 = el / den;
    float svm = 1.0f / (1.0f + expf(-wr_yvm[0]));
    float thr = expf(b0_yrm[0]);

    float a = wb1 / so;           // z_oo = b0_yom + (c0 - mo)*a
    g_par[0] = -LOG2E * a;
    g_par[1] = -LOG2E * (b0_yom[0] - mo * a);
    g_par[2] = oo1;
    g_par[3] = ol1;
    g_par[4] = svm;
    g_par[5] = thr;
    g_par[6] = thr * 500.0f;
    float al = wb2 / SL_C;        // z_ol = b0_ylm + (u2 - ML)*al
    g_par[7] = -LOG2E * al;
    g_par[8] = -LOG2E * (b0_ylm[0] - ML_C * al);
    g_acc[0] = 0.0;
    g_acc[1] = 0.0;
}

// ---------------------------------------------------------------------------
// Precompute ol[i] = ol1 * sigmoid(b0_ylm + (u2-ML)/SL*wb2)  (input-only gate)
__global__ void k_prepass(const float2* __restrict__ x, int n) {
    int i = blockIdx.x * blockDim.x + threadIdx.x;
    if (i >= n) return;
    float u2 = x[i].y;
    float t = fmaf(u2, g_par[7], g_par[8]);
    float e;
    asm("ex2.approx.f32 %0, %1;" : "=f"(e) : "f"(t));
    g_ol[i] = g_par[3] / (1.0f + e);
}

// ---------------------------------------------------------------------------
__global__ void k_reduce(const float* __restrict__ y, int ny) {
    int hi = TRAINN < ny ? TRAINN : ny;
    int count = hi - SPIN;
    double s = 0.0, s2 = 0.0;
    for (int i = blockIdx.x * blockDim.x + threadIdx.x; i < count;
         i += gridDim.x * blockDim.x) {
        double v = (double)y[SPIN + i];
        s  += v;
        s2 += v * v;
    }
    #pragma unroll
    for (int o = 16; o; o >>= 1) {
        s  += __shfl_down_sync(0xFFFFFFFFu, s,  o);
        s2 += __shfl_down_sync(0xFFFFFFFFu, s2, o);
    }
    if ((threadIdx.x & 31) == 0) {
        atomicAdd(&g_acc[0], s);
        atomicAdd(&g_acc[1], s2);
    }
}

__global__ void k_finalize(int ny) {
    int hi = TRAINN < ny ? TRAINN : ny;
    double cnt = (double)(hi - SPIN);
    double var = (g_acc[1] - g_acc[0] * g_acc[0] / cnt) / (cnt - 1.0);
    g_par[9] = (float)sqrt(var > 0.0 ? var : 0.0);
}

// ---------------------------------------------------------------------------
// Speculative chunk-parallel recurrence.
// The map c0 -> c1 is strongly contracting (relaxation toward K=thr*500 with
// |dc1/dc0| ~ f - svm << 1), so each chunk runs a WARM-step burn-in from c=0;
// by the chunk's core region the speculative state has converged to the true
// trajectory far below fp32 resolution. Chunk 0 is exact (no warm-up).
// Within a block: thread 0 runs the scalar recurrence off smem tiles staged
// by all threads. Per-step math is branch-free (all selects are FSELs):
//   cl = max( fma(-oo1*c0, r, Bv - sg*absd),
//             fma( oo1*(absd-c0), r, (Bv - absd) + oab) )
//   r = rcp(1 + exp2(A2*c0 + B2)) (oo-sigmoid), Bv = c0 + u1 - olc*c0
__global__ void __launch_bounds__(SEQ_THREADS, 1)
k_scan(const float2* __restrict__ x, int n, const int* __restrict__ tlp) {
    __shared__ float4 sin_[TILE];   // (u1, u2, ol, -)
    __shared__ float  ssc[TILE];    // state entering each step

    int tl = tlp[0];
    if (tl < 0) tl = 0;
    if (tl > n) tl = n;
    int nrem = n - tl;
    if (nrem <= 0) return;

    int L  = (nrem + CHUNKS - 1) / CHUNKS;    // core length per chunk
    int cs = tl + (int)blockIdx.x * L;        // core start (global index)
    if (cs >= n) return;
    int ce = cs + L; if (ce > n) ce = n;      // core end
    int ws = cs - WARM; if (ws < tl) ws = tl; // warm-up start

    float A2  = g_par[0], B2 = g_par[1], oo1 = g_par[2];
    float svm = g_par[4], thr = g_par[5], K = g_par[6];
    float noo1 = -oo1, nsvm = -svm, mthr = -thr;

    float c = 0.0f;
    for (int base = ws; base < ce; base += TILE) {
        int lim = ce - base; if (lim > TILE) lim = TILE;

        for (int j = threadIdx.x; j < lim; j += SEQ_THREADS) {
            float2 xv = x[base + j];
            sin_[j] = make_float4(xv.x, xv.y, g_ol[base + j], 0.0f);
        }
        __syncthreads();

        if (threadIdx.x == 0) {
            float cl = c;
            #pragma unroll 4
            for (int j = 0; j < lim; j++) {
                float4 v = sin_[j];               // u1=v.x u2=v.y ol=v.z
                float c0 = cl;
                ssc[j] = c0;

                // critical chain: c0 -> t -> e -> d -> r
                float t = fmaf(c0, A2, B2);
                float e;  asm("ex2.approx.f32 %0, %1;" : "=f"(e) : "f"(t));
                float d = 1.0f + e;
                float r;  asm("rcp.approx.f32 %0, %1;" : "=f"(r) : "f"(d));
                float rc; asm("rcp.approx.f32 %0, %1;" : "=f"(rc) : "f"(c0));

                bool  pos  = c0 > 0.0f;
                float absd = fabsf(c0 - K);
                float olc0 = v.z * c0;
                float mn   = fminf(olc0, v.y);
                float mlc  = pos ? mn : olc0;              // olc*c0
                float Bv   = (c0 + v.x) - mlc;

                float s   = fmaf(c0, 0.002f, mthr);
                float sgp = (s > 0.0f) ? svm : 0.0f;       // flat FSELs
                float sg  = (s < 0.0f) ? nsvm : sgp;
                float C1  = fmaf(-sg, absd, Bv);
                float k1  = noo1 * c0;

                float qa   = v.y * absd;
                float qr   = qa * rc;
                float ola  = v.z * absd;
                float oabm = fminf(ola, qr);
                float oab  = pos ? oabm : ola;             // olc*absd
                float k2   = oo1 * (absd - c0);
                float C2   = (Bv - absd) + oab;

                float a1 = fmaf(k1, r, C1);
                float a2 = fmaf(k2, r, C2);
                cl = fmaxf(a1, a2);
            }
            c = cl;
        }
        __syncthreads();

        // Drain states, core region only
        int lo = cs - base; if (lo < 0) lo = 0;
        for (int j = lo + (int)threadIdx.x; j < lim; j += SEQ_THREADS)
            g_c[base + j] = ssc[j];
        __syncthreads();
    }
}

// ---------------------------------------------------------------------------
// Parallel epilogue: recompute gates from the state trajectory.
// Layout: [h_n | c_n | l_n | lc_n | z | z | Goo | Gol | Golc | Gf |
//          h_nout(N,2 interleaved) | obs_std | Gov]
__global__ void k_out(const float2* __restrict__ x, int n,
                      const int* __restrict__ tlp, float* __restrict__ out) {
    int i = blockIdx.x * blockDim.x + threadIdx.x;
    if (i >= n) return;
    int tl = tlp[0];
    long long nn = n;
    if (i < tl) {
        out[i] = 0.0f;            out[nn + i] = 0.0f;
        out[2*nn + i] = 0.0f;     out[3*nn + i] = 0.0f;
        out[4*nn + i] = 0.0f;     out[5*nn + i] = 0.0f;
        out[6*nn + i] = 0.0f;     out[7*nn + i] = 0.0f;
        out[8*nn + i] = 0.0f;     out[9*nn + i] = 0.0f;
        out[10*nn + 2*(long long)i]     = 0.0f;
        out[10*nn + 2*(long long)i + 1] = 0.0f;
        out[12*nn + i] = 0.0f;    out[13*nn + i] = 0.0f;
        return;
    }
    float c0 = g_c[i];
    float u2 = x[i].y;
    float ol = g_ol[i];
    float thr = g_par[5], svm = g_par[4];

    float t = fmaf(c0, g_par[0], g_par[1]);
    float e;  asm("ex2.approx.f32 %0, %1;" : "=f"(e) : "f"(t));
    float oo = g_par[2] / (1.0f + e);
    float olc;
    if (c0 > 0.0f) olc = fminf(ol, u2 / c0); else olc = ol;
    float f = (1.0f - oo) - olc;
    float s = fmaf(c0, 0.002f, -thr);
    float sg = (s > 0.0f) ? svm : ((s < 0.0f) ? -svm : 0.0f);
    float ov = fminf(sg, f);
    float obss = g_par[9];
    float h = oo * c0;

    out[i]         = h;
    out[nn + i]    = c0;
    out[2*nn + i]  = ol * c0;
    out[3*nn + i]  = olc * c0;
    out[4*nn + i]  = 0.0f;
    out[5*nn + i]  = 0.0f;
    out[6*nn + i]  = oo;
    out[7*nn + i]  = ol;
    out[8*nn + i]  = olc;
    out[9*nn + i]  = f;
    out[10*nn + 2*(long long)i]     = h;
    out[10*nn + 2*(long long)i + 1] = obss;
    out[12*nn + i] = obss;
    out[13*nn + i] = ov;
}

// ---------------------------------------------------------------------------
extern "C" void kernel_launch(void* const* d_in, const int* in_sizes, int n_in,
                              void* d_out, int out_size) {
    const float2* x   = (const float2*)d_in[0];
    const float*  y   = (const float*)d_in[1];
    const float*  pm  = (const float*)d_in[2];
    const float*  ps  = (const float*)d_in[3];
    const float*  wr_yom = (const float*)d_in[4];
    const float*  wr_ylm = (const float*)d_in[5];
    const float*  wr_yfm = (const float*)d_in[6];
    const float*  wr_yvm = (const float*)d_in[7];
    const float*  b0_yom = (const float*)d_in[8];
    const float*  wb1    = (const float*)d_in[9];
    const float*  b0_ylm = (const float*)d_in[10];
    const float*  wb2    = (const float*)d_in[11];
    const float*  b0_yrm = (const float*)d_in[12];
    const int*    tlp    = (const int*)d_in[14];   // time_lag
    float* out = (float*)d_out;
    (void)n_in; (void)out_size;

    int n  = in_sizes[0] / 2;
    if (n > MAXN) n = MAXN;
    int ny = in_sizes[1];

    k_setup<<<1, 1>>>(pm, ps, wr_yom, wr_ylm, wr_yfm, wr_yvm,
                      b0_yom, wb1, b0_ylm, wb2, b0_yrm);
    k_prepass<<<(n + 255) / 256, 256>>>(x, n);
    k_reduce<<<160, 256>>>(y, ny);
    k_finalize<<<1, 1>>>(ny);
    k_scan<<<CHUNKS, SEQ_THREADS>>>(x, n, tlp);
    k_out<<<(n + 255) / 256, 256>>>(x, n, tlp, out);
}

// round 6
// speedup vs baseline: 531.8111x; 5.4212x over previous
#include <cuda_runtime.h>
#include <math.h>

// Problem constants (from reference)
#define MAXN   524288
#define SPIN   1000
#define TRAINN 400000
#define ML_C   2.9086f
#define SL_C   1.898f

#define CHUNKS 4096       // one lane per chunk
#define WARM   512        // speculative warm-up steps (contraction burn-in)
#define SCAN_TPB 64

// Scratch (no allocations allowed)
__device__ float  g_c[MAXN];     // state entering each step
__device__ double g_acc[2];      // sum, sumsq for obsstd
__device__ float  g_par[12];
// g_par: 0=A2 1=B2 (exp2 coeffs: exp(-z_oo)=exp2(A2*c0+B2))
//        2=oo1 3=ol1 4=svm 5=thr 6=K(=thr*500) 7=AL 8=BL 9=obsstd

// ---------------------------------------------------------------------------
__global__ void k_setup(const float* pm, const float* ps,
                        const float* wr_yom, const float* wr_ylm,
                        const float* wr_yfm, const float* wr_yvm,
                        const float* b0_yom, const float* wb1p,
                        const float* b0_ylm, const float* wb2p,
                        const float* b0_yrm) {
    const float LOG2E = 1.4426950408889634f;
    float mo = pm[0], so = ps[0];
    float wb1 = wb1p[0], wb2 = wb2p[0];
    float eo = expf(wr_yom[0]);
    float el = expf(wr_ylm[0]);
    float ef = expf(wr_yfm[0]);
    float den = eo + el + ef;
    float oo1 = eo / den;
    float ol1 = el / den;
    float svm = 1.0f / (1.0f + expf(-wr_yvm[0]));
    float thr = expf(b0_yrm[0]);

    float a = wb1 / so;           // z_oo = b0_yom + (c0 - mo)*a
    g_par[0] = -LOG2E * a;
    g_par[1] = -LOG2E * (b0_yom[0] - mo * a);
    g_par[2] = oo1;
    g_par[3] = ol1;
    g_par[4] = svm;
    g_par[5] = thr;
    g_par[6] = thr * 500.0f;
    float al = wb2 / SL_C;        // z_ol = b0_ylm + (u2 - ML)*al
    g_par[7] = -LOG2E * al;
    g_par[8] = -LOG2E * (b0_ylm[0] - ML_C * al);
    g_acc[0] = 0.0;
    g_acc[1] = 0.0;
}

// ---------------------------------------------------------------------------
__global__ void k_reduce(const float* __restrict__ y, int ny) {
    int hi = TRAINN < ny ? TRAINN : ny;
    int count = hi - SPIN;
    double s = 0.0, s2 = 0.0;
    for (int i = blockIdx.x * blockDim.x + threadIdx.x; i < count;
         i += gridDim.x * blockDim.x) {
        double v = (double)y[SPIN + i];
        s  += v;
        s2 += v * v;
    }
    #pragma unroll
    for (int o = 16; o; o >>= 1) {
        s  += __shfl_down_sync(0xFFFFFFFFu, s,  o);
        s2 += __shfl_down_sync(0xFFFFFFFFu, s2, o);
    }
    if ((threadIdx.x & 31) == 0) {
        atomicAdd(&g_acc[0], s);
        atomicAdd(&g_acc[1], s2);
    }
}

__global__ void k_finalize(int ny) {
    int hi = TRAINN < ny ? TRAINN : ny;
    double cnt = (double)(hi - SPIN);
    double var = (g_acc[1] - g_acc[0] * g_acc[0] / cnt) / (cnt - 1.0);
    g_par[9] = (float)sqrt(var > 0.0 ? var : 0.0);
}

// ---------------------------------------------------------------------------
struct Par {
    float A2, B2, oo1, noo1, svm, nsvm, mthr, K, AL, BL, ol1;
};

__device__ __forceinline__ float olgate(float u2, const Par& p) {
    float t = fmaf(u2, p.AL, p.BL);
    float e; asm("ex2.approx.f32 %0, %1;" : "=f"(e) : "f"(t));
    float r; asm("rcp.approx.f32 %0, %1;" : "=f"(r) : "f"(1.0f + e));
    return p.ol1 * r;
}

// One recurrence step (branch-free; all selects are FSELs).
//   cl = max( fma(-oo1*c0, r, Bv - sg*absd),
//             fma( oo1*(absd-c0), r, (Bv - absd) + olc*absd) )
//   r  = rcp(1 + exp2(A2*c0 + B2))   (the oo-sigmoid)
//   Bv = c0 + u1 - olc*c0
__device__ __forceinline__ float stepf(float c0, float u1, float u2, float ol,
                                       const Par& p) {
    float t = fmaf(c0, p.A2, p.B2);
    float e;  asm("ex2.approx.f32 %0, %1;" : "=f"(e) : "f"(t));
    float d = 1.0f + e;
    float r;  asm("rcp.approx.f32 %0, %1;" : "=f"(r) : "f"(d));
    float rc; asm("rcp.approx.f32 %0, %1;" : "=f"(rc) : "f"(c0));

    bool  pos  = c0 > 0.0f;
    float absd = fabsf(c0 - p.K);
    float olc0 = ol * c0;
    float mn   = fminf(olc0, u2);
    float mlc  = pos ? mn : olc0;              // olc*c0
    float Bv   = (c0 + u1) - mlc;

    float s   = fmaf(c0, 0.002f, p.mthr);
    float sgp = (s > 0.0f) ? p.svm : 0.0f;
    float sg  = (s < 0.0f) ? p.nsvm : sgp;
    float C1  = fmaf(-sg, absd, Bv);
    float k1  = p.noo1 * c0;

    float qa   = u2 * absd;
    float qr   = qa * rc;
    float ola  = ol * absd;
    float oabm = fminf(ola, qr);
    float oab  = pos ? oabm : ola;             // olc*absd
    float k2   = p.oo1 * (absd - c0);
    float C2   = (Bv - absd) + oab;

    return fmaxf(fmaf(k1, r, C1), fmaf(k2, r, C2));
}

// ---------------------------------------------------------------------------
// Warp-SIMD speculative chunks: lane = chunk. Each lane runs WARM burn-in
// steps from c=0 (contraction makes the speculative state converge to the
// true trajectory far below fp32 resolution), then L core steps writing the
// state trajectory. Chunk 0's warm region is clipped at tl, so it is exact
// and anchors the whole sequence. Input-only ol gate is software-pipelined
// one step ahead to keep it off the critical chain.
__global__ void __launch_bounds__(SCAN_TPB, 1)
k_scan(const float2* __restrict__ x, int n, const int* __restrict__ tlp) {
    int tl = tlp[0];
    if (tl < 0) tl = 0;
    if (tl > n) tl = n;
    int nrem = n - tl;
    if (nrem <= 0) return;
    int L   = (nrem + CHUNKS - 1) / CHUNKS;
    int nch = (nrem + L - 1) / L;
    int c   = blockIdx.x * blockDim.x + threadIdx.x;
    if (c >= nch) return;

    Par p;
    p.A2 = g_par[0]; p.B2 = g_par[1]; p.oo1 = g_par[2]; p.noo1 = -p.oo1;
    p.svm = g_par[4]; p.nsvm = -p.svm; p.mthr = -g_par[5]; p.K = g_par[6];
    p.AL = g_par[7]; p.BL = g_par[8]; p.ol1 = g_par[3];

    int cs = tl + c * L;
    int ce = cs + L; if (ce > n) ce = n;

    float cl = 0.0f;
    int i = cs - WARM;

    // pipeline head: input + ol for the first step
    int idx0 = i < 0 ? 0 : i;
    float2 xv = x[idx0];
    float  ol = olgate(xv.y, p);

    // ---- warm-up (discarded) ----
    #pragma unroll 4
    for (int j = 0; j < WARM; j++, i++) {
        int inx = i + 1;
        int idx = inx < 0 ? 0 : inx;            // inx <= cs < n always
        float2 xn = x[idx];
        int pf = inx + 64; if (pf >= n) pf = n - 1;
        asm volatile("prefetch.global.L1 [%0];" :: "l"(x + pf));
        float oln = olgate(xn.y, p);
        float cn  = stepf(cl, xv.x, xv.y, ol, p);
        cl = (i >= tl) ? cn : cl;
        xv = xn; ol = oln;
    }

    // ---- core (writes trajectory) ----
    #pragma unroll 4
    for (; i < ce; i++) {
        g_c[i] = cl;                             // state ENTERING step i
        int inx = i + 1; if (inx >= n) inx = n - 1;
        float2 xn = x[inx];
        int pf = inx + 64; if (pf >= n) pf = n - 1;
        asm volatile("prefetch.global.L1 [%0];" :: "l"(x + pf));
        float oln = olgate(xn.y, p);
        cl = stepf(cl, xv.x, xv.y, ol, p);
        xv = xn; ol = oln;
    }
}

// ---------------------------------------------------------------------------
// Parallel epilogue: recompute gates from the state trajectory.
// Layout: [h_n | c_n | l_n | lc_n | z | z | Goo | Gol | Golc | Gf |
//          h_nout(N,2 interleaved) | obs_std | Gov]
__global__ void k_out(const float2* __restrict__ x, int n,
                      const int* __restrict__ tlp, float* __restrict__ out) {
    int i = blockIdx.x * blockDim.x + threadIdx.x;
    if (i >= n) return;
    int tl = tlp[0];
    long long nn = n;
    if (i < tl) {
        out[i] = 0.0f;            out[nn + i] = 0.0f;
        out[2*nn + i] = 0.0f;     out[3*nn + i] = 0.0f;
        out[4*nn + i] = 0.0f;     out[5*nn + i] = 0.0f;
        out[6*nn + i] = 0.0f;     out[7*nn + i] = 0.0f;
        out[8*nn + i] = 0.0f;     out[9*nn + i] = 0.0f;
        out[10*nn + 2*(long long)i]     = 0.0f;
        out[10*nn + 2*(long long)i + 1] = 0.0f;
        out[12*nn + i] = 0.0f;    out[13*nn + i] = 0.0f;
        return;
    }
    float c0 = g_c[i];
    float2 xv = x[i];
    float u2 = xv.y;
    float thr = g_par[5], svm = g_par[4];

    // ol gate inline
    float t2 = fmaf(u2, g_par[7], g_par[8]);
    float e2; asm("ex2.approx.f32 %0, %1;" : "=f"(e2) : "f"(t2));
    float ol = g_par[3] / (1.0f + e2);

    float t = fmaf(c0, g_par[0], g_par[1]);
    float e;  asm("ex2.approx.f32 %0, %1;" : "=f"(e) : "f"(t));
    float oo = g_par[2] / (1.0f + e);
    float olc;
    if (c0 > 0.0f) olc = fminf(ol, u2 / c0); else olc = ol;
    float f = (1.0f - oo) - olc;
    float s = fmaf(c0, 0.002f, -thr);
    float sg = (s > 0.0f) ? svm : ((s < 0.0f) ? -svm : 0.0f);
    float ov = fminf(sg, f);
    float obss = g_par[9];
    float h = oo * c0;

    out[i]         = h;
    out[nn + i]    = c0;
    out[2*nn + i]  = ol * c0;
    out[3*nn + i]  = olc * c0;
    out[4*nn + i]  = 0.0f;
    out[5*nn + i]  = 0.0f;
    out[6*nn + i]  = oo;
    out[7*nn + i]  = ol;
    out[8*nn + i]  = olc;
    out[9*nn + i]  = f;
    out[10*nn + 2*(long long)i]     = h;
    out[10*nn + 2*(long long)i + 1] = obss;
    out[12*nn + i] = obss;
    out[13*nn + i] = ov;
}

// ---------------------------------------------------------------------------
extern "C" void kernel_launch(void* const* d_in, const int* in_sizes, int n_in,
                              void* d_out, int out_size) {
    const float2* x   = (const float2*)d_in[0];
    const float*  y   = (const float*)d_in[1];
    const float*  pm  = (const float*)d_in[2];
    const float*  ps  = (const float*)d_in[3];
    const float*  wr_yom = (const float*)d_in[4];
    const float*  wr_ylm = (const float*)d_in[5];
    const float*  wr_yfm = (const float*)d_in[6];
    const float*  wr_yvm = (const float*)d_in[7];
    const float*  b0_yom = (const float*)d_in[8];
    const float*  wb1    = (const float*)d_in[9];
    const float*  b0_ylm = (const float*)d_in[10];
    const float*  wb2    = (const float*)d_in[11];
    const float*  b0_yrm = (const float*)d_in[12];
    const int*    tlp    = (const int*)d_in[14];   // time_lag
    float* out = (float*)d_out;
    (void)n_in; (void)out_size;

    int n  = in_sizes[0] / 2;
    if (n > MAXN) n = MAXN;
    int ny = in_sizes[1];

    k_setup<<<1, 1>>>(pm, ps, wr_yom, wr_ylm, wr_yfm, wr_yvm,
                      b0_yom, wb1, b0_ylm, wb2, b0_yrm);
    k_reduce<<<160, 256>>>(y, ny);
    k_finalize<<<1, 1>>>(ny);
    k_scan<<<CHUNKS / SCAN_TPB, SCAN_TPB>>>(x, n, tlp);
    k_out<<<(n + 255) / 256, 256>>>(x, n, tlp, out);
}

// round 7
// speedup vs baseline: 833.8433x; 1.5679x over previous
#include <cuda_runtime.h>
#include <math.h>

// Problem constants (from reference)
#define MAXN   524288
#define SPIN   1000
#define TRAINN 400000
#define ML_C   2.9086f
#define SL_C   1.898f

#define CHUNKS 8192       // one lane per chunk  (L = 64 at full size)
#define WARM   128        // speculative warm-up steps (contraction: rho <= 0.5)
#define TSTEP  32         // steps staged per tile
#define LMAX   64         // max core length per chunk
#define SCAN_TPB 64

// Scratch (no allocations allowed)
__device__ float  g_c[MAXN];     // state entering each step
__device__ double g_acc[2];      // sum, sumsq for obsstd
__device__ float  g_par[12];
// g_par: 0=A2 1=B2 (exp2 coeffs: exp(-z_oo)=exp2(A2*c0+B2))
//        2=oo1 3=ol1 4=svm 5=thr 6=K(=thr*500) 7=AL 8=BL 9=obsstd

// ---------------------------------------------------------------------------
__global__ void k_setup(const float* pm, const float* ps,
                        const float* wr_yom, const float* wr_ylm,
                        const float* wr_yfm, const float* wr_yvm,
                        const float* b0_yom, const float* wb1p,
                        const float* b0_ylm, const float* wb2p,
                        const float* b0_yrm) {
    const float LOG2E = 1.4426950408889634f;
    float mo = pm[0], so = ps[0];
    float wb1 = wb1p[0], wb2 = wb2p[0];
    float eo = expf(wr_yom[0]);
    float el = expf(wr_ylm[0]);
    float ef = expf(wr_yfm[0]);
    float den = eo + el + ef;
    float oo1 = eo / den;
    float ol1 = el / den;
    float svm = 1.0f / (1.0f + expf(-wr_yvm[0]));
    float thr = expf(b0_yrm[0]);

    float a = wb1 / so;           // z_oo = b0_yom + (c0 - mo)*a
    g_par[0] = -LOG2E * a;
    g_par[1] = -LOG2E * (b0_yom[0] - mo * a);
    g_par[2] = oo1;
    g_par[3] = ol1;
    g_par[4] = svm;
    g_par[5] = thr;
    g_par[6] = thr * 500.0f;
    float al = wb2 / SL_C;        // z_ol = b0_ylm + (u2 - ML)*al
    g_par[7] = -LOG2E * al;
    g_par[8] = -LOG2E * (b0_ylm[0] - ML_C * al);
    g_acc[0] = 0.0;
    g_acc[1] = 0.0;
}

// ---------------------------------------------------------------------------
__global__ void k_reduce(const float* __restrict__ y, int ny) {
    int hi = TRAINN < ny ? TRAINN : ny;
    int count = hi - SPIN;
    double s = 0.0, s2 = 0.0;
    for (int i = blockIdx.x * blockDim.x + threadIdx.x; i < count;
         i += gridDim.x * blockDim.x) {
        double v = (double)y[SPIN + i];
        s  += v;
        s2 += v * v;
    }
    #pragma unroll
    for (int o = 16; o; o >>= 1) {
        s  += __shfl_down_sync(0xFFFFFFFFu, s,  o);
        s2 += __shfl_down_sync(0xFFFFFFFFu, s2, o);
    }
    if ((threadIdx.x & 31) == 0) {
        atomicAdd(&g_acc[0], s);
        atomicAdd(&g_acc[1], s2);
    }
}

__global__ void k_finalize(int ny) {
    int hi = TRAINN < ny ? TRAINN : ny;
    double cnt = (double)(hi - SPIN);
    double var = (g_acc[1] - g_acc[0] * g_acc[0] / cnt) / (cnt - 1.0);
    g_par[9] = (float)sqrt(var > 0.0 ? var : 0.0);
}

// ---------------------------------------------------------------------------
struct Par {
    float A2, B2, oo1, noo1, svm, nsvm, mthr, K, AL, BL, ol1;
};

__device__ __forceinline__ float olgate(float u2, const Par& p) {
    float t = fmaf(u2, p.AL, p.BL);
    float e; asm("ex2.approx.f32 %0, %1;" : "=f"(e) : "f"(t));
    float r; asm("rcp.approx.f32 %0, %1;" : "=f"(r) : "f"(1.0f + e));
    return p.ol1 * r;
}

// One recurrence step (branch-free; all selects are FSELs).
__device__ __forceinline__ float stepf(float c0, float u1, float u2, float ol,
                                       const Par& p) {
    float t = fmaf(c0, p.A2, p.B2);
    float e;  asm("ex2.approx.f32 %0, %1;" : "=f"(e) : "f"(t));
    float d = 1.0f + e;
    float r;  asm("rcp.approx.f32 %0, %1;" : "=f"(r) : "f"(d));
    float rc; asm("rcp.approx.f32 %0, %1;" : "=f"(rc) : "f"(c0));

    bool  pos  = c0 > 0.0f;
    float absd = fabsf(c0 - p.K);
    float olc0 = ol * c0;
    float mn   = fminf(olc0, u2);
    float mlc  = pos ? mn : olc0;              // olc*c0
    float Bv   = (c0 + u1) - mlc;

    float s   = fmaf(c0, 0.002f, p.mthr);
    float sgp = (s > 0.0f) ? p.svm : 0.0f;
    float sg  = (s < 0.0f) ? p.nsvm : sgp;
    float C1  = fmaf(-sg, absd, Bv);
    float k1  = p.noo1 * c0;

    float qa   = u2 * absd;
    float qr   = qa * rc;
    float ola  = ol * absd;
    float oabm = fminf(ola, qr);
    float oab  = pos ? oabm : ola;             // olc*absd
    float k2   = p.oo1 * (absd - c0);
    float C2   = (Bv - absd) + oab;

    return fmaxf(fmaf(k1, r, C1), fmaf(k2, r, C2));
}

// ---------------------------------------------------------------------------
// Warp-SIMD speculative chunks with smem-transpose staging.
// Each warp owns 32 consecutive chunks (lane = chunk). Per TSTEP tile the
// warp coalescedly loads 32 contiguous segments into padded smem, computes
// TSTEP steps off conflict-free LDS, buffers core states in smem, and drains
// them with coalesced stores at the end. WARM-step burn-in from c=0: the map
// is contracting with |dc1/dc0| = f - svm <= 0.5 in all regimes, so the
// speculative state converges to the true trajectory below fp32 resolution.
__global__ void __launch_bounds__(SCAN_TPB, 1)
k_scan(const float2* __restrict__ x, int n, const int* __restrict__ tlp) {
    __shared__ float su1[SCAN_TPB/32][32][TSTEP + 1];
    __shared__ float su2[SCAN_TPB/32][32][TSTEP + 1];
    __shared__ float ssc[SCAN_TPB/32][32][LMAX + 1];

    int tl = tlp[0];
    if (tl < 0) tl = 0;
    if (tl > n) tl = n;
    int nrem = n - tl;
    if (nrem <= 0) return;
    int L   = (nrem + CHUNKS - 1) / CHUNKS;   // <= LMAX
    int nch = (nrem + L - 1) / L;

    int wid  = threadIdx.x >> 5;
    int lane = threadIdx.x & 31;
    int wch0 = (blockIdx.x * (SCAN_TPB / 32) + wid) * 32; // warp's first chunk
    if (wch0 >= nch) return;

    Par p;
    p.A2 = g_par[0]; p.B2 = g_par[1]; p.oo1 = g_par[2]; p.noo1 = -p.oo1;
    p.svm = g_par[4]; p.nsvm = -p.svm; p.mthr = -g_par[5]; p.K = g_par[6];
    p.AL = g_par[7]; p.BL = g_par[8]; p.ol1 = g_par[3];

    int c      = wch0 + lane;                 // this lane's chunk
    int gate_j = WARM - c * L;                // step j admits update iff j>=gate_j
    int base_i = tl + wch0 * L - WARM;        // global i of (segment 0, j=0)

    const int warm_rounds = WARM / TSTEP;
    int core_rounds = (L + TSTEP - 1) / TSTEP;

    float cl = 0.0f;
    for (int rd = 0; rd < warm_rounds + core_rounds; rd++) {
        int j0 = rd * TSTEP;
        // --- coalesced staging: segment s, element `lane` ---
        #pragma unroll 4
        for (int s = 0; s < 32; s++) {
            int idx = base_i + s * L + j0 + lane;
            idx = idx < 0 ? 0 : (idx >= n ? n - 1 : idx);
            float2 v = x[idx];
            su1[wid][s][lane] = v.x;
            su2[wid][s][lane] = v.y;
        }
        __syncwarp();

        if (rd < warm_rounds) {
            #pragma unroll
            for (int jj = 0; jj < TSTEP; jj++) {
                float u1 = su1[wid][lane][jj];
                float u2 = su2[wid][lane][jj];
                float ol = olgate(u2, p);
                float cn = stepf(cl, u1, u2, ol, p);
                cl = (j0 + jj >= gate_j) ? cn : cl;   // gated only in warm phase
            }
        } else {
            int jc0 = j0 - WARM;
            #pragma unroll
            for (int jj = 0; jj < TSTEP; jj++) {
                int jc = jc0 + jj;
                if (jc < L) ssc[wid][lane][jc] = cl;  // state ENTERING step
                float u1 = su1[wid][lane][jj];
                float u2 = su2[wid][lane][jj];
                float ol = olgate(u2, p);
                cl = stepf(cl, u1, u2, ol, p);
            }
        }
        __syncwarp();
    }

    // --- coalesced drain of core trajectories ---
    for (int s = 0; s < 32; s++) {
        int ch = wch0 + s;
        if (ch >= nch) break;
        int cbase = tl + ch * L;
        for (int e = lane; e < L; e += 32) {
            int gi = cbase + e;
            if (gi < n) g_c[gi] = ssc[wid][s][e];
        }
    }
}

// ---------------------------------------------------------------------------
// Parallel epilogue: recompute gates from the state trajectory.
// Layout: [h_n | c_n | l_n | lc_n | z | z | Goo | Gol | Golc | Gf |
//          h_nout(N,2 interleaved) | obs_std | Gov]
__global__ void k_out(const float2* __restrict__ x, int n,
                      const int* __restrict__ tlp, float* __restrict__ out) {
    int i = blockIdx.x * blockDim.x + threadIdx.x;
    if (i >= n) return;
    int tl = tlp[0];
    long long nn = n;
    if (i < tl) {
        out[i] = 0.0f;            out[nn + i] = 0.0f;
        out[2*nn + i] = 0.0f;     out[3*nn + i] = 0.0f;
        out[4*nn + i] = 0.0f;     out[5*nn + i] = 0.0f;
        out[6*nn + i] = 0.0f;     out[7*nn + i] = 0.0f;
        out[8*nn + i] = 0.0f;     out[9*nn + i] = 0.0f;
        out[10*nn + 2*(long long)i]     = 0.0f;
        out[10*nn + 2*(long long)i + 1] = 0.0f;
        out[12*nn + i] = 0.0f;    out[13*nn + i] = 0.0f;
        return;
    }
    float c0 = g_c[i];
    float2 xv = x[i];
    float u2 = xv.y;
    float thr = g_par[5], svm = g_par[4];

    // ol gate inline
    float t2 = fmaf(u2, g_par[7], g_par[8]);
    float e2; asm("ex2.approx.f32 %0, %1;" : "=f"(e2) : "f"(t2));
    float ol = g_par[3] / (1.0f + e2);

    float t = fmaf(c0, g_par[0], g_par[1]);
    float e;  asm("ex2.approx.f32 %0, %1;" : "=f"(e) : "f"(t));
    float oo = g_par[2] / (1.0f + e);
    float olc;
    if (c0 > 0.0f) olc = fminf(ol, u2 / c0); else olc = ol;
    float f = (1.0f - oo) - olc;
    float s = fmaf(c0, 0.002f, -thr);
    float sg = (s > 0.0f) ? svm : ((s < 0.0f) ? -svm : 0.0f);
    float ov = fminf(sg, f);
    float obss = g_par[9];
    float h = oo * c0;

    out[i]         = h;
    out[nn + i]    = c0;
    out[2*nn + i]  = ol * c0;
    out[3*nn + i]  = olc * c0;
    out[4*nn + i]  = 0.0f;
    out[5*nn + i]  = 0.0f;
    out[6*nn + i]  = oo;
    out[7*nn + i]  = ol;
    out[8*nn + i]  = olc;
    out[9*nn + i]  = f;
    out[10*nn + 2*(long long)i]     = h;
    out[10*nn + 2*(long long)i + 1] = obss;
    out[12*nn + i] = obss;
    out[13*nn + i] = ov;
}

// ---------------------------------------------------------------------------
extern "C" void kernel_launch(void* const* d_in, const int* in_sizes, int n_in,
                              void* d_out, int out_size) {
    const float2* x   = (const float2*)d_in[0];
    const float*  y   = (const float*)d_in[1];
    const float*  pm  = (const float*)d_in[2];
    const float*  ps  = (const float*)d_in[3];
    const float*  wr_yom = (const float*)d_in[4];
    const float*  wr_ylm = (const float*)d_in[5];
    const float*  wr_yfm = (const float*)d_in[6];
    const float*  wr_yvm = (const float*)d_in[7];
    const float*  b0_yom = (const float*)d_in[8];
    const float*  wb1    = (const float*)d_in[9];
    const float*  b0_ylm = (const float*)d_in[10];
    const float*  wb2    = (const float*)d_in[11];
    const float*  b0_yrm = (const float*)d_in[12];
    const int*    tlp    = (const int*)d_in[14];   // time_lag
    float* out = (float*)d_out;
    (void)n_in; (void)out_size;

    int n  = in_sizes[0] / 2;
    if (n > MAXN) n = MAXN;
    int ny = in_sizes[1];

    k_setup<<<1, 1>>>(pm, ps, wr_yom, wr_ylm, wr_yfm, wr_yvm,
                      b0_yom, wb1, b0_ylm, wb2, b0_yrm);
    k_reduce<<<160, 256>>>(y, ny);
    k_finalize<<<1, 1>>>(ny);
    k_scan<<<CHUNKS / SCAN_TPB, SCAN_TPB>>>(x, n, tlp);
    k_out<<<(n + 255) / 256, 256>>>(x, n, tlp, out);
}

// round 8
// speedup vs baseline: 873.3974x; 1.0474x over previous
#include <cuda_runtime.h>
#include <math.h>

// Problem constants (from reference)
#define MAXN   524288
#define SPIN   1000
#define TRAINN 400000
#define ML_C   2.9086f
#define SL_C   1.898f

#define L_C    64                 // core steps per chunk (lane)
#define WARM   128                // speculative burn-in (contraction rho<=0.5)
#define STEPS  (WARM + L_C)       // 192 sequential steps per lane
#define SPAN   (31*L_C + STEPS)   // 2176 unique elements per warp
#define SU_SZ  3300               // > SWZ(SPAN) = 3298
#define SWZ(o) ((o) + 33*((o) >> 6))
#define SCAN_TPB 64
#define SCAN_BLOCKS 128
#define SCAN_SMEM ((4*SU_SZ + 2*32*65) * 4)   // bytes
#define REDB   160

// Scratch (no allocations allowed)
__device__ float    g_c[MAXN];      // state entering each step
__device__ double   g_part[REDB*2]; // per-block partial sums
__device__ unsigned g_ctr = 0;      // completion counter (self-resetting)
__device__ float    g_par[12];
// g_par: 0=A2 1=B2 (exp2 coeffs: exp(-z_oo)=exp2(A2*c0+B2))
//        2=oo1 3=ol1 4=svm 5=thr 6=K(=thr*500) 7=AL 8=BL 9=obsstd

// ---------------------------------------------------------------------------
// Fused: block 0 thread 0 computes the derived parameters; every block
// reduces its slice of y into g_part; the last-finishing block combines the
// partials into obsstd (g_par[9]) and resets the counter for graph replay.
__global__ void k_reduce(const float* __restrict__ y, int ny,
                         const float* pm, const float* ps,
                         const float* wr_yom, const float* wr_ylm,
                         const float* wr_yfm, const float* wr_yvm,
                         const float* b0_yom, const float* wb1p,
                         const float* b0_ylm, const float* wb2p,
                         const float* b0_yrm) {
    if (blockIdx.x == 0 && threadIdx.x == 0) {
        const float LOG2E = 1.4426950408889634f;
        float mo = pm[0], so = ps[0];
        float wb1 = wb1p[0], wb2 = wb2p[0];
        float eo = expf(wr_yom[0]);
        float el = expf(wr_ylm[0]);
        float ef = expf(wr_yfm[0]);
        float den = eo + el + ef;
        float a = wb1 / so;
        g_par[0] = -LOG2E * a;
        g_par[1] = -LOG2E * (b0_yom[0] - mo * a);
        g_par[2] = eo / den;
        g_par[3] = el / den;
        g_par[4] = 1.0f / (1.0f + expf(-wr_yvm[0]));
        float thr = expf(b0_yrm[0]);
        g_par[5] = thr;
        g_par[6] = thr * 500.0f;
        float al = wb2 / SL_C;
        g_par[7] = -LOG2E * al;
        g_par[8] = -LOG2E * (b0_ylm[0] - ML_C * al);
    }

    int hi = TRAINN < ny ? TRAINN : ny;
    int count = hi - SPIN;
    double s = 0.0, s2 = 0.0;
    for (int i = blockIdx.x * blockDim.x + threadIdx.x; i < count;
         i += gridDim.x * blockDim.x) {
        double v = (double)y[SPIN + i];
        s  += v;
        s2 += v * v;
    }
    #pragma unroll
    for (int o = 16; o; o >>= 1) {
        s  += __shfl_down_sync(0xFFFFFFFFu, s,  o);
        s2 += __shfl_down_sync(0xFFFFFFFFu, s2, o);
    }
    __shared__ double ws[8][2];
    __shared__ int    lastf;
    int wid = threadIdx.x >> 5;
    if ((threadIdx.x & 31) == 0) { ws[wid][0] = s; ws[wid][1] = s2; }
    __syncthreads();
    if (threadIdx.x == 0) {
        double bs = 0.0, bs2 = 0.0;
        #pragma unroll
        for (int w = 0; w < 8; w++) { bs += ws[w][0]; bs2 += ws[w][1]; }
        g_part[2*blockIdx.x]     = bs;
        g_part[2*blockIdx.x + 1] = bs2;
        __threadfence();
        unsigned t = atomicAdd(&g_ctr, 1u);
        lastf = (t == gridDim.x - 1) ? 1 : 0;
    }
    __syncthreads();
    if (lastf && threadIdx.x == 0) {
        double ts = 0.0, ts2 = 0.0;
        for (int b = 0; b < REDB; b++) { ts += g_part[2*b]; ts2 += g_part[2*b+1]; }
        double cnt = (double)count;
        float res = 0.0f;
        if (count > 1) {
            double var = (ts2 - ts * ts / cnt) / (cnt - 1.0);
            res = (float)sqrt(var > 0.0 ? var : 0.0);
        }
        g_par[9] = res;
        g_ctr = 0;                // reset for next graph replay
    }
}

// ---------------------------------------------------------------------------
struct Par {
    float A2, B2, oo1, noo1, svm, nsvm, mthr, K, AL, BL, ol1;
};

__device__ __forceinline__ float olgate(float u2, const Par& p) {
    float t = fmaf(u2, p.AL, p.BL);
    float e; asm("ex2.approx.f32 %0, %1;" : "=f"(e) : "f"(t));
    float r; asm("rcp.approx.f32 %0, %1;" : "=f"(r) : "f"(1.0f + e));
    return p.ol1 * r;
}

// One recurrence step (branch-free; all selects are FSELs).
__device__ __forceinline__ float stepf(float c0, float u1, float u2, float ol,
                                       const Par& p) {
    float t = fmaf(c0, p.A2, p.B2);
    float e;  asm("ex2.approx.f32 %0, %1;" : "=f"(e) : "f"(t));
    float d = 1.0f + e;
    float r;  asm("rcp.approx.f32 %0, %1;" : "=f"(r) : "f"(d));
    float rc; asm("rcp.approx.f32 %0, %1;" : "=f"(rc) : "f"(c0));

    bool  pos  = c0 > 0.0f;
    float absd = fabsf(c0 - p.K);
    float olc0 = ol * c0;
    float mn   = fminf(olc0, u2);
    float mlc  = pos ? mn : olc0;              // olc*c0
    float Bv   = (c0 + u1) - mlc;

    float s   = fmaf(c0, 0.002f, p.mthr);
    float sgp = (s > 0.0f) ? p.svm : 0.0f;
    float sg  = (s < 0.0f) ? p.nsvm : sgp;
    float C1  = fmaf(-sg, absd, Bv);
    float k1  = p.noo1 * c0;

    float qa   = u2 * absd;
    float qr   = qa * rc;
    float ola  = ol * absd;
    float oabm = fminf(ola, qr);
    float oab  = pos ? oabm : ola;             // olc*absd
    float k2   = p.oo1 * (absd - c0);
    float C2   = (Bv - absd) + oab;

    return fmaxf(fmaf(k1, r, C1), fmaf(k2, r, C2));
}

// ---------------------------------------------------------------------------
// Warp-SIMD speculative chunks, single-shot staging.
// Each warp owns 32 consecutive chunks (lane = chunk, L_C=64 core steps).
// The warp's full unique input span (SPAN=2176 elements) is staged ONCE with
// coalesced loads into a flat smem array under the arithmetic swizzle
// sigma(o)=o+33*(o>>6), which is bank-conflict-free both for the coalesced
// stores (o = 32m+lane) and the compute reads (o = 64*lane + j).
// Then 192 uninterrupted steps: WARM burn-in from c=0 (contraction makes the
// speculative state converge below fp32 resolution; chunks 0,1 are exactly
// gated) followed by L_C core steps buffered in smem and drained coalesced.
__global__ void __launch_bounds__(SCAN_TPB, 1)
k_scan(const float2* __restrict__ x, int n, const int* __restrict__ tlp) {
    extern __shared__ float smem[];
    int wid  = threadIdx.x >> 5;
    int lane = threadIdx.x & 31;
    float* su1 = smem + wid * SU_SZ;
    float* su2 = smem + 2 * SU_SZ + wid * SU_SZ;
    float* ssc = smem + 4 * SU_SZ + wid * (32 * 65);

    int tl = tlp[0];
    if (tl < 0) tl = 0;
    if (tl > n) tl = n;
    int nrem = n - tl;
    if (nrem <= 0) return;
    int nch = (nrem + L_C - 1) / L_C;

    int wch0 = (blockIdx.x * 2 + wid) * 32;   // warp's first chunk
    if (wch0 >= nch) return;

    Par p;
    p.A2 = g_par[0]; p.B2 = g_par[1]; p.oo1 = g_par[2]; p.noo1 = -p.oo1;
    p.svm = g_par[4]; p.nsvm = -p.svm; p.mthr = -g_par[5]; p.K = g_par[6];
    p.AL = g_par[7]; p.BL = g_par[8]; p.ol1 = g_par[3];

    int spanbase = tl + wch0 * L_C - WARM;

    // ---- single-shot coalesced staging of the warp's span ----
    #pragma unroll 8
    for (int o = lane; o < SPAN; o += 32) {
        int idx = spanbase + o;
        idx = idx < 0 ? 0 : (idx >= n ? n - 1 : idx);
        float2 v = x[idx];
        int so = SWZ(o);
        su1[so] = v.x;
        su2[so] = v.y;
    }
    __syncwarp();

    int gate_j  = WARM - (wch0 + lane) * L_C;  // update admitted iff j >= gate_j
    int base_o  = lane * L_C;

    float cl = 0.0f;
    // pipeline head: inputs + ol for step 0
    int o0 = SWZ(base_o);
    float u1n = su1[o0], u2n = su2[o0];
    float oln = olgate(u2n, p);

    // ---- warm-up (discarded; gated so chunks 0,1 are exact) ----
    #pragma unroll 4
    for (int j = 0; j < WARM; j++) {
        float u1 = u1n, u2 = u2n, ol = oln;
        int on = SWZ(base_o + j + 1);
        u1n = su1[on]; u2n = su2[on];
        oln = olgate(u2n, p);
        float cn = stepf(cl, u1, u2, ol, p);
        cl = (j >= gate_j) ? cn : cl;
    }

    // ---- core (buffers trajectory in smem) ----
    #pragma unroll 4
    for (int j = 0; j < L_C; j++) {
        ssc[lane * 65 + j] = cl;               // state ENTERING this step
        float u1 = u1n, u2 = u2n, ol = oln;
        int on = SWZ(base_o + WARM + j + 1);   // max 3298 < SU_SZ
        u1n = su1[on]; u2n = su2[on];
        oln = olgate(u2n, p);
        cl = stepf(cl, u1, u2, ol, p);
    }
    __syncwarp();

    // ---- coalesced drain ----
    for (int s = 0; s < 32; s++) {
        int ch = wch0 + s;
        if (ch >= nch) break;
        int cbase = tl + ch * L_C;
        #pragma unroll
        for (int e = lane; e < L_C; e += 32) {
            int gi = cbase + e;
            if (gi < n) g_c[gi] = ssc[s * 65 + e];
        }
    }
}

// ---------------------------------------------------------------------------
// Parallel epilogue: recompute gates from the state trajectory.
// Layout: [h_n | c_n | l_n | lc_n | z | z | Goo | Gol | Golc | Gf |
//          h_nout(N,2 interleaved) | obs_std | Gov]
__global__ void k_out(const float2* __restrict__ x, int n,
                      const int* __restrict__ tlp, float* __restrict__ out) {
    int i = blockIdx.x * blockDim.x + threadIdx.x;
    if (i >= n) return;
    int tl = tlp[0];
    long long nn = n;
    if (i < tl) {
        out[i] = 0.0f;            out[nn + i] = 0.0f;
        out[2*nn + i] = 0.0f;     out[3*nn + i] = 0.0f;
        out[4*nn + i] = 0.0f;     out[5*nn + i] = 0.0f;
        out[6*nn + i] = 0.0f;     out[7*nn + i] = 0.0f;
        out[8*nn + i] = 0.0f;     out[9*nn + i] = 0.0f;
        out[10*nn + 2*(long long)i]     = 0.0f;
        out[10*nn + 2*(long long)i + 1] = 0.0f;
        out[12*nn + i] = 0.0f;    out[13*nn + i] = 0.0f;
        return;
    }
    float c0 = g_c[i];
    float2 xv = x[i];
    float u2 = xv.y;
    float thr = g_par[5], svm = g_par[4];

    // ol gate inline
    float t2 = fmaf(u2, g_par[7], g_par[8]);
    float e2; asm("ex2.approx.f32 %0, %1;" : "=f"(e2) : "f"(t2));
    float ol = g_par[3] / (1.0f + e2);

    float t = fmaf(c0, g_par[0], g_par[1]);
    float e;  asm("ex2.approx.f32 %0, %1;" : "=f"(e) : "f"(t));
    float oo = g_par[2] / (1.0f + e);
    float olc;
    if (c0 > 0.0f) olc = fminf(ol, u2 / c0); else olc = ol;
    float f = (1.0f - oo) - olc;
    float s = fmaf(c0, 0.002f, -thr);
    float sg = (s > 0.0f) ? svm : ((s < 0.0f) ? -svm : 0.0f);
    float ov = fminf(sg, f);
    float obss = g_par[9];
    float h = oo * c0;

    out[i]         = h;
    out[nn + i]    = c0;
    out[2*nn + i]  = ol * c0;
    out[3*nn + i]  = olc * c0;
    out[4*nn + i]  = 0.0f;
    out[5*nn + i]  = 0.0f;
    out[6*nn + i]  = oo;
    out[7*nn + i]  = ol;
    out[8*nn + i]  = olc;
    out[9*nn + i]  = f;
    out[10*nn + 2*(long long)i]     = h;
    out[10*nn + 2*(long long)i + 1] = obss;
    out[12*nn + i] = obss;
    out[13*nn + i] = ov;
}

// ---------------------------------------------------------------------------
extern "C" void kernel_launch(void* const* d_in, const int* in_sizes, int n_in,
                              void* d_out, int out_size) {
    const float2* x   = (const float2*)d_in[0];
    const float*  y   = (const float*)d_in[1];
    const float*  pm  = (const float*)d_in[2];
    const float*  ps  = (const float*)d_in[3];
    const float*  wr_yom = (const float*)d_in[4];
    const float*  wr_ylm = (const float*)d_in[5];
    const float*  wr_yfm = (const float*)d_in[6];
    const float*  wr_yvm = (const float*)d_in[7];
    const float*  b0_yom = (const float*)d_in[8];
    const float*  wb1    = (const float*)d_in[9];
    const float*  b0_ylm = (const float*)d_in[10];
    const float*  wb2    = (const float*)d_in[11];
    const float*  b0_yrm = (const float*)d_in[12];
    const int*    tlp    = (const int*)d_in[14];   // time_lag
    float* out = (float*)d_out;
    (void)n_in; (void)out_size;

    int n  = in_sizes[0] / 2;
    if (n > MAXN) n = MAXN;
    int ny = in_sizes[1];

    cudaFuncSetAttribute(k_scan, cudaFuncAttributeMaxDynamicSharedMemorySize,
                         SCAN_SMEM);

    k_reduce<<<REDB, 256>>>(y, ny, pm, ps, wr_yom, wr_ylm, wr_yfm, wr_yvm,
                            b0_yom, wb1, b0_ylm, wb2, b0_yrm);
    k_scan<<<SCAN_BLOCKS, SCAN_TPB, SCAN_SMEM>>>(x, n, tlp);
    k_out<<<(n + 255) / 256, 256>>>(x, n, tlp, out);
}

// round 9
// speedup vs baseline: 1236.3883x; 1.4156x over previous
#include <cuda_runtime.h>
#include <math.h>

// Problem constants (from reference)
#define MAXN   524288
#define SPIN   1000
#define TRAINN 400000
#define ML_C   2.9086f
#define SL_C   1.898f

#define L_C    64                 // core steps per chunk (lane)
#define WARM   64                 // speculative burn-in (contraction rho<=0.5)
#define STEPS  (WARM + L_C)       // 128 sequential steps per lane
#define SPAN   (31*L_C + STEPS)   // 2112 unique elements per warp
#define SU_SZ  3208               // >= SWZ(SPAN)=3201 (+pad)
#define SWZ(o) ((o) + 33*((o) >> 6))
#define SCAN_TPB 64
#define SCAN_BLOCKS 128
#define REDB2   64                // reduce blocks appended to the scan grid
#define TOT_BLOCKS (SCAN_BLOCKS + REDB2)
#define SCAN_SMEM ((4*SU_SZ + 2*32*65) * 4)   // bytes

// Scratch (no allocations allowed)
__device__ float    g_c[MAXN];        // state entering each step
__device__ double   g_part[REDB2*2];  // per-block partial sums
__device__ unsigned g_ctr = 0;        // completion counter (self-resetting)
__device__ float    g_obs[1];         // obsstd result

// ---------------------------------------------------------------------------
struct Par {
    float A2, B2, oo1, noo1, svm, nsvm, mthr, K, AL, BL, ol1;
};

__device__ __forceinline__ Par make_par(
        const float* pm, const float* ps,
        const float* wr_yom, const float* wr_ylm,
        const float* wr_yfm, const float* wr_yvm,
        const float* b0_yom, const float* wb1p,
        const float* b0_ylm, const float* wb2p,
        const float* b0_yrm) {
    const float LOG2E = 1.4426950408889634f;
    Par p;
    float eo = expf(wr_yom[0]);
    float el = expf(wr_ylm[0]);
    float ef = expf(wr_yfm[0]);
    float den = eo + el + ef;
    p.oo1  = eo / den;
    p.ol1  = el / den;
    p.noo1 = -p.oo1;
    p.svm  = 1.0f / (1.0f + expf(-wr_yvm[0]));
    p.nsvm = -p.svm;
    float thr = expf(b0_yrm[0]);
    p.mthr = -thr;
    p.K    = thr * 500.0f;
    float a = wb1p[0] / ps[0];
    p.A2 = -LOG2E * a;
    p.B2 = -LOG2E * (b0_yom[0] - pm[0] * a);
    float al = wb2p[0] / SL_C;
    p.AL = -LOG2E * al;
    p.BL = -LOG2E * (b0_ylm[0] - ML_C * al);
    return p;
}

__device__ __forceinline__ float olgate(float u2, const Par& p) {
    float t = fmaf(u2, p.AL, p.BL);
    float e; asm("ex2.approx.f32 %0, %1;" : "=f"(e) : "f"(t));
    float r; asm("rcp.approx.f32 %0, %1;" : "=f"(r) : "f"(1.0f + e));
    return p.ol1 * r;
}

// One recurrence step (branch-free; all selects are FSELs).
__device__ __forceinline__ float stepf(float c0, float u1, float u2, float ol,
                                       const Par& p) {
    float t = fmaf(c0, p.A2, p.B2);
    float e;  asm("ex2.approx.f32 %0, %1;" : "=f"(e) : "f"(t));
    float d = 1.0f + e;
    float r;  asm("rcp.approx.f32 %0, %1;" : "=f"(r) : "f"(d));
    float rc; asm("rcp.approx.f32 %0, %1;" : "=f"(rc) : "f"(c0));

    bool  pos  = c0 > 0.0f;
    float absd = fabsf(c0 - p.K);
    float olc0 = ol * c0;
    float mn   = fminf(olc0, u2);
    float mlc  = pos ? mn : olc0;              // olc*c0
    float Bv   = (c0 + u1) - mlc;

    float s   = fmaf(c0, 0.002f, p.mthr);
    float sgp = (s > 0.0f) ? p.svm : 0.0f;
    float sg  = (s < 0.0f) ? p.nsvm : sgp;
    float C1  = fmaf(-sg, absd, Bv);
    float k1  = p.noo1 * c0;

    float qa   = u2 * absd;
    float qr   = qa * rc;
    float ola  = ol * absd;
    float oabm = fminf(ola, qr);
    float oab  = pos ? oabm : ola;             // olc*absd
    float k2   = p.oo1 * (absd - c0);
    float C2   = (Bv - absd) + oab;

    return fmaxf(fmaf(k1, r, C1), fmaf(k2, r, C2));
}

// ---------------------------------------------------------------------------
// Fused kernel. Blocks [0, SCAN_BLOCKS): warp-SIMD speculative chunk scan
// (each block computes its own derived params — no cross-block dependency).
// Blocks [SCAN_BLOCKS, TOT_BLOCKS): fp32 obsstd reduction running
// concurrently; last-finishing reduce block combines partials in fp64
// (parallel shuffle) and publishes g_obs.
__global__ void __launch_bounds__(SCAN_TPB, 1)
k_main(const float2* __restrict__ x, int n, const int* __restrict__ tlp,
       const float* __restrict__ y, int ny,
       const float* pm, const float* ps,
       const float* wr_yom, const float* wr_ylm,
       const float* wr_yfm, const float* wr_yvm,
       const float* b0_yom, const float* wb1p,
       const float* b0_ylm, const float* wb2p,
       const float* b0_yrm) {
    extern __shared__ float smem[];

    if (blockIdx.x >= SCAN_BLOCKS) {
        // ---------------- obsstd reduction (fp32 accumulate) ----------------
        __shared__ double rsh[2][2];
        __shared__ int    lastf;
        int rb  = blockIdx.x - SCAN_BLOCKS;
        int tid = threadIdx.x;
        int hi = TRAINN < ny ? TRAINN : ny;
        int count = hi - SPIN;
        float s = 0.0f, s2 = 0.0f;
        for (int i = rb * SCAN_TPB + tid; i < count; i += REDB2 * SCAN_TPB) {
            float v = y[SPIN + i];
            s += v;
            s2 = fmaf(v, v, s2);
        }
        #pragma unroll
        for (int o = 16; o; o >>= 1) {
            s  += __shfl_down_sync(0xFFFFFFFFu, s,  o);
            s2 += __shfl_down_sync(0xFFFFFFFFu, s2, o);
        }
        int w = tid >> 5;
        if ((tid & 31) == 0) { rsh[w][0] = (double)s; rsh[w][1] = (double)s2; }
        __syncthreads();
        if (tid == 0) {
            g_part[2*rb]     = rsh[0][0] + rsh[1][0];
            g_part[2*rb + 1] = rsh[0][1] + rsh[1][1];
            __threadfence();
            unsigned t = atomicAdd(&g_ctr, 1u);
            lastf = (t == REDB2 - 1) ? 1 : 0;
        }
        __syncthreads();
        if (lastf) {
            double ds = 0.0, ds2 = 0.0;
            if (tid < REDB2) { ds = g_part[2*tid]; ds2 = g_part[2*tid + 1]; }
            #pragma unroll
            for (int o = 16; o; o >>= 1) {
                ds  += __shfl_down_sync(0xFFFFFFFFu, ds,  o);
                ds2 += __shfl_down_sync(0xFFFFFFFFu, ds2, o);
            }
            if ((tid & 31) == 0) { rsh[tid >> 5][0] = ds; rsh[tid >> 5][1] = ds2; }
            __syncthreads();
            if (tid == 0) {
                double ts  = rsh[0][0] + rsh[1][0];
                double ts2 = rsh[0][1] + rsh[1][1];
                double cnt = (double)count;
                float res = 0.0f;
                if (count > 1) {
                    double var = (ts2 - ts * ts / cnt) / (cnt - 1.0);
                    res = (float)sqrt(var > 0.0 ? var : 0.0);
                }
                g_obs[0] = res;
                g_ctr = 0;            // reset for next graph replay
            }
        }
        return;
    }

    // ------------------------------ scan ------------------------------
    int wid  = threadIdx.x >> 5;
    int lane = threadIdx.x & 31;
    float* su1 = smem + wid * SU_SZ;
    float* su2 = smem + 2 * SU_SZ + wid * SU_SZ;
    float* ssc = smem + 4 * SU_SZ + wid * (32 * 65);

    int tl = tlp[0];
    if (tl < 0) tl = 0;
    if (tl > n) tl = n;
    int nrem = n - tl;
    if (nrem <= 0) return;
    int nch = (nrem + L_C - 1) / L_C;

    int wch0 = (blockIdx.x * 2 + wid) * 32;   // warp's first chunk
    if (wch0 >= nch) return;

    Par p = make_par(pm, ps, wr_yom, wr_ylm, wr_yfm, wr_yvm,
                     b0_yom, wb1p, b0_ylm, wb2p, b0_yrm);

    int spanbase = tl + wch0 * L_C - WARM;

    // ---- single-shot coalesced staging of the warp's span ----
    #pragma unroll 8
    for (int o = lane; o < SPAN; o += 32) {
        int idx = spanbase + o;
        idx = idx < 0 ? 0 : (idx >= n ? n - 1 : idx);
        float2 v = x[idx];
        int so = SWZ(o);
        su1[so] = v.x;
        su2[so] = v.y;
    }
    __syncwarp();

    int gate_j = WARM - (wch0 + lane) * L_C;  // update admitted iff j >= gate_j
    int base_o = lane * L_C;

    float cl = 0.0f;
    int o0 = SWZ(base_o);
    float u1n = su1[o0], u2n = su2[o0];
    float oln = olgate(u2n, p);

    // ---- warm-up (discarded; gated so chunk 0 is exact) ----
    #pragma unroll 4
    for (int j = 0; j < WARM; j++) {
        float u1 = u1n, u2 = u2n, ol = oln;
        int on = SWZ(base_o + j + 1);
        u1n = su1[on]; u2n = su2[on];
        oln = olgate(u2n, p);
        float cn = stepf(cl, u1, u2, ol, p);
        cl = (j >= gate_j) ? cn : cl;
    }

    // ---- core (buffers trajectory in smem) ----
    #pragma unroll 4
    for (int j = 0; j < L_C; j++) {
        ssc[lane * 65 + j] = cl;               // state ENTERING this step
        float u1 = u1n, u2 = u2n, ol = oln;
        int on = SWZ(base_o + WARM + j + 1);   // max SWZ(2112)=3201 < SU_SZ
        u1n = su1[on]; u2n = su2[on];
        oln = olgate(u2n, p);
        cl = stepf(cl, u1, u2, ol, p);
    }
    __syncwarp();

    // ---- coalesced drain ----
    for (int s = 0; s < 32; s++) {
        int ch = wch0 + s;
        if (ch >= nch) break;
        int cbase = tl + ch * L_C;
        #pragma unroll
        for (int e = lane; e < L_C; e += 32) {
            int gi = cbase + e;
            if (gi < n) g_c[gi] = ssc[s * 65 + e];
        }
    }
}

// ---------------------------------------------------------------------------
// Parallel epilogue: recompute gates from the state trajectory.
// Layout: [h_n | c_n | l_n | lc_n | z | z | Goo | Gol | Golc | Gf |
//          h_nout(N,2 interleaved) | obs_std | Gov]
__global__ void k_out(const float2* __restrict__ x, int n,
                      const int* __restrict__ tlp, float* __restrict__ out,
                      const float* pm, const float* ps,
                      const float* wr_yom, const float* wr_ylm,
                      const float* wr_yfm, const float* wr_yvm,
                      const float* b0_yom, const float* wb1p,
                      const float* b0_ylm, const float* wb2p,
                      const float* b0_yrm) {
    __shared__ Par sp;
    __shared__ float sobs;
    if (threadIdx.x == 0) {
        sp = make_par(pm, ps, wr_yom, wr_ylm, wr_yfm, wr_yvm,
                      b0_yom, wb1p, b0_ylm, wb2p, b0_yrm);
        sobs = g_obs[0];
    }
    __syncthreads();

    int i = blockIdx.x * blockDim.x + threadIdx.x;
    if (i >= n) return;
    int tl = tlp[0];
    long long nn = n;
    if (i < tl) {
        out[i] = 0.0f;            out[nn + i] = 0.0f;
        out[2*nn + i] = 0.0f;     out[3*nn + i] = 0.0f;
        out[4*nn + i] = 0.0f;     out[5*nn + i] = 0.0f;
        out[6*nn + i] = 0.0f;     out[7*nn + i] = 0.0f;
        out[8*nn + i] = 0.0f;     out[9*nn + i] = 0.0f;
        out[10*nn + 2*(long long)i]     = 0.0f;
        out[10*nn + 2*(long long)i + 1] = 0.0f;
        out[12*nn + i] = 0.0f;    out[13*nn + i] = 0.0f;
        return;
    }
    float c0 = g_c[i];
    float2 xv = x[i];
    float u2 = xv.y;
    float thr = -sp.mthr, svm = sp.svm;

    float ol = olgate(u2, sp);

    float t = fmaf(c0, sp.A2, sp.B2);
    float e;  asm("ex2.approx.f32 %0, %1;" : "=f"(e) : "f"(t));
    float oo = sp.oo1 / (1.0f + e);
    float olc;
    if (c0 > 0.0f) olc = fminf(ol, u2 / c0); else olc = ol;
    float f = (1.0f - oo) - olc;
    float s = fmaf(c0, 0.002f, -thr);
    float sg = (s > 0.0f) ? svm : ((s < 0.0f) ? -svm : 0.0f);
    float ov = fminf(sg, f);
    float obss = sobs;
    float h = oo * c0;

    out[i]         = h;
    out[nn + i]    = c0;
    out[2*nn + i]  = ol * c0;
    out[3*nn + i]  = olc * c0;
    out[4*nn + i]  = 0.0f;
    out[5*nn + i]  = 0.0f;
    out[6*nn + i]  = oo;
    out[7*nn + i]  = ol;
    out[8*nn + i]  = olc;
    out[9*nn + i]  = f;
    out[10*nn + 2*(long long)i]     = h;
    out[10*nn + 2*(long long)i + 1] = obss;
    out[12*nn + i] = obss;
    out[13*nn + i] = ov;
}

// ---------------------------------------------------------------------------
extern "C" void kernel_launch(void* const* d_in, const int* in_sizes, int n_in,
                              void* d_out, int out_size) {
    const float2* x   = (const float2*)d_in[0];
    const float*  y   = (const float*)d_in[1];
    const float*  pm  = (const float*)d_in[2];
    const float*  ps  = (const float*)d_in[3];
    const float*  wr_yom = (const float*)d_in[4];
    const float*  wr_ylm = (const float*)d_in[5];
    const float*  wr_yfm = (const float*)d_in[6];
    const float*  wr_yvm = (const float*)d_in[7];
    const float*  b0_yom = (const float*)d_in[8];
    const float*  wb1    = (const float*)d_in[9];
    const float*  b0_ylm = (const float*)d_in[10];
    const float*  wb2    = (const float*)d_in[11];
    const float*  b0_yrm = (const float*)d_in[12];
    const int*    tlp    = (const int*)d_in[14];   // time_lag
    float* out = (float*)d_out;
    (void)n_in; (void)out_size;

    int n  = in_sizes[0] / 2;
    if (n > MAXN) n = MAXN;
    int ny = in_sizes[1];

    cudaFuncSetAttribute(k_main, cudaFuncAttributeMaxDynamicSharedMemorySize,
                         SCAN_SMEM);

    k_main<<<TOT_BLOCKS, SCAN_TPB, SCAN_SMEM>>>(x, n, tlp, y, ny,
        pm, ps, wr_yom, wr_ylm, wr_yfm, wr_yvm,
        b0_yom, wb1, b0_ylm, wb2, b0_yrm);
    k_out<<<(n + 255) / 256, 256>>>(x, n, tlp, out,
        pm, ps, wr_yom, wr_ylm, wr_yfm, wr_yvm,
        b0_yom, wb1, b0_ylm, wb2, b0_yrm);
}

// round 10
// speedup vs baseline: 1737.8827x; 1.4056x over previous
#include <cuda_runtime.h>
#include <math.h>

// Problem constants (from reference)
#define MAXN   524288
#define SPIN   1000
#define TRAINN 400000
#define ML_C   2.9086f
#define SL_C   1.898f

#define L_C    64                 // core steps per chunk (lane)
#define WARM   64                 // speculative burn-in (contraction rho<=0.5)
#define STEPS  (WARM + L_C)       // 128 sequential steps per lane
#define SPAN   (31*L_C + STEPS)   // 2112 unique elements per warp
#define SU_SZ  3208               // >= SWZ(SPAN)=3201 (+pad)
#define SWZ(o) ((o) + 33*((o) >> 6))
#define SCAN_TPB 64
#define SCAN_BLOCKS 128
#define REDB2   64                // reduce blocks appended to the scan grid
#define TOT_BLOCKS (SCAN_BLOCKS + REDB2)
#define SCAN_SMEM ((4*SU_SZ + 2*32*65) * 4)   // bytes

// Scratch (no allocations allowed)
__device__ float    g_c[MAXN];        // state entering each step
__device__ double   g_part[REDB2*2];  // per-block partial sums
__device__ unsigned g_ctr = 0;        // completion counter (self-resetting)
__device__ float    g_obs[1];         // obsstd result

// ---------------------------------------------------------------------------
struct Par {
    float A2, B2, oo1, noo1, svm, nsvm, mthr, K, AL, BL, ol1;
};

__device__ __forceinline__ Par make_par(
        const float* pm, const float* ps,
        const float* wr_yom, const float* wr_ylm,
        const float* wr_yfm, const float* wr_yvm,
        const float* b0_yom, const float* wb1p,
        const float* b0_ylm, const float* wb2p,
        const float* b0_yrm) {
    const float LOG2E = 1.4426950408889634f;
    Par p;
    float eo = expf(wr_yom[0]);
    float el = expf(wr_ylm[0]);
    float ef = expf(wr_yfm[0]);
    float den = eo + el + ef;
    p.oo1  = eo / den;
    p.ol1  = el / den;
    p.noo1 = -p.oo1;
    p.svm  = 1.0f / (1.0f + expf(-wr_yvm[0]));
    p.nsvm = -p.svm;
    float thr = expf(b0_yrm[0]);
    p.mthr = -thr;
    p.K    = thr * 500.0f;
    float a = wb1p[0] / ps[0];
    p.A2 = -LOG2E * a;
    p.B2 = -LOG2E * (b0_yom[0] - pm[0] * a);
    float al = wb2p[0] / SL_C;
    p.AL = -LOG2E * al;
    p.BL = -LOG2E * (b0_ylm[0] - ML_C * al);
    return p;
}

__device__ __forceinline__ float olgate(float u2, const Par& p) {
    float t = fmaf(u2, p.AL, p.BL);
    float e; asm("ex2.approx.f32 %0, %1;" : "=f"(e) : "f"(t));
    float r; asm("rcp.approx.f32 %0, %1;" : "=f"(r) : "f"(1.0f + e));
    return p.ol1 * r;
}

// One recurrence step (branch-free; all selects are FSELs).
__device__ __forceinline__ float stepf(float c0, float u1, float u2, float ol,
                                       const Par& p) {
    float t = fmaf(c0, p.A2, p.B2);
    float e;  asm("ex2.approx.f32 %0, %1;" : "=f"(e) : "f"(t));
    float d = 1.0f + e;
    float r;  asm("rcp.approx.f32 %0, %1;" : "=f"(r) : "f"(d));
    float rc; asm("rcp.approx.f32 %0, %1;" : "=f"(rc) : "f"(c0));

    bool  pos  = c0 > 0.0f;
    float absd = fabsf(c0 - p.K);
    float olc0 = ol * c0;
    float mn   = fminf(olc0, u2);
    float mlc  = pos ? mn : olc0;              // olc*c0
    float Bv   = (c0 + u1) - mlc;

    float s   = fmaf(c0, 0.002f, p.mthr);
    float sgp = (s > 0.0f) ? p.svm : 0.0f;
    float sg  = (s < 0.0f) ? p.nsvm : sgp;
    float C1  = fmaf(-sg, absd, Bv);
    float k1  = p.noo1 * c0;

    float qa   = u2 * absd;
    float qr   = qa * rc;
    float ola  = ol * absd;
    float oabm = fminf(ola, qr);
    float oab  = pos ? oabm : ola;             // olc*absd
    float k2   = p.oo1 * (absd - c0);
    float C2   = (Bv - absd) + oab;

    return fmaxf(fmaf(k1, r, C1), fmaf(k2, r, C2));
}

// ---------------------------------------------------------------------------
// Fused kernel: scan blocks + concurrent obsstd-reduce blocks (see R9).
__global__ void __launch_bounds__(SCAN_TPB, 1)
k_main(const float2* __restrict__ x, int n, const int* __restrict__ tlp,
       const float* __restrict__ y, int ny,
       const float* pm, const float* ps,
       const float* wr_yom, const float* wr_ylm,
       const float* wr_yfm, const float* wr_yvm,
       const float* b0_yom, const float* wb1p,
       const float* b0_ylm, const float* wb2p,
       const float* b0_yrm) {
    extern __shared__ float smem[];

    if (blockIdx.x >= SCAN_BLOCKS) {
        // ---------------- obsstd reduction (fp32 accumulate) ----------------
        __shared__ double rsh[2][2];
        __shared__ int    lastf;
        int rb  = blockIdx.x - SCAN_BLOCKS;
        int tid = threadIdx.x;
        int hi = TRAINN < ny ? TRAINN : ny;
        int count = hi - SPIN;
        float s = 0.0f, s2 = 0.0f;
        for (int i = rb * SCAN_TPB + tid; i < count; i += REDB2 * SCAN_TPB) {
            float v = y[SPIN + i];
            s += v;
            s2 = fmaf(v, v, s2);
        }
        #pragma unroll
        for (int o = 16; o; o >>= 1) {
            s  += __shfl_down_sync(0xFFFFFFFFu, s,  o);
            s2 += __shfl_down_sync(0xFFFFFFFFu, s2, o);
        }
        int w = tid >> 5;
        if ((tid & 31) == 0) { rsh[w][0] = (double)s; rsh[w][1] = (double)s2; }
        __syncthreads();
        if (tid == 0) {
            g_part[2*rb]     = rsh[0][0] + rsh[1][0];
            g_part[2*rb + 1] = rsh[0][1] + rsh[1][1];
            __threadfence();
            unsigned t = atomicAdd(&g_ctr, 1u);
            lastf = (t == REDB2 - 1) ? 1 : 0;
        }
        __syncthreads();
        if (lastf) {
            double ds = 0.0, ds2 = 0.0;
            if (tid < REDB2) { ds = g_part[2*tid]; ds2 = g_part[2*tid + 1]; }
            #pragma unroll
            for (int o = 16; o; o >>= 1) {
                ds  += __shfl_down_sync(0xFFFFFFFFu, ds,  o);
                ds2 += __shfl_down_sync(0xFFFFFFFFu, ds2, o);
            }
            if ((tid & 31) == 0) { rsh[tid >> 5][0] = ds; rsh[tid >> 5][1] = ds2; }
            __syncthreads();
            if (tid == 0) {
                double ts  = rsh[0][0] + rsh[1][0];
                double ts2 = rsh[0][1] + rsh[1][1];
                double cnt = (double)count;
                float res = 0.0f;
                if (count > 1) {
                    double var = (ts2 - ts * ts / cnt) / (cnt - 1.0);
                    res = (float)sqrt(var > 0.0 ? var : 0.0);
                }
                g_obs[0] = res;
                g_ctr = 0;            // reset for next graph replay
            }
        }
        return;
    }

    // ------------------------------ scan ------------------------------
    int wid  = threadIdx.x >> 5;
    int lane = threadIdx.x & 31;
    float* su1 = smem + wid * SU_SZ;
    float* su2 = smem + 2 * SU_SZ + wid * SU_SZ;
    float* ssc = smem + 4 * SU_SZ + wid * (32 * 65);

    int tl = tlp[0];
    if (tl < 0) tl = 0;
    if (tl > n) tl = n;
    int nrem = n - tl;
    if (nrem <= 0) return;
    int nch = (nrem + L_C - 1) / L_C;

    int wch0 = (blockIdx.x * 2 + wid) * 32;   // warp's first chunk
    if (wch0 >= nch) return;

    Par p = make_par(pm, ps, wr_yom, wr_ylm, wr_yfm, wr_yvm,
                     b0_yom, wb1p, b0_ylm, wb2p, b0_yrm);

    int spanbase = tl + wch0 * L_C - WARM;

    // ---- single-shot coalesced staging of the warp's span ----
    #pragma unroll 8
    for (int o = lane; o < SPAN; o += 32) {
        int idx = spanbase + o;
        idx = idx < 0 ? 0 : (idx >= n ? n - 1 : idx);
        float2 v = x[idx];
        int so = SWZ(o);
        su1[so] = v.x;
        su2[so] = v.y;
    }
    __syncwarp();

    int gate_j = WARM - (wch0 + lane) * L_C;  // update admitted iff j >= gate_j
    int base_o = lane * L_C;

    float cl = 0.0f;
    int o0 = SWZ(base_o);
    float u1n = su1[o0], u2n = su2[o0];
    float oln = olgate(u2n, p);

    // ---- warm-up (discarded; gated so chunk 0 is exact) ----
    #pragma unroll 4
    for (int j = 0; j < WARM; j++) {
        float u1 = u1n, u2 = u2n, ol = oln;
        int on = SWZ(base_o + j + 1);
        u1n = su1[on]; u2n = su2[on];
        oln = olgate(u2n, p);
        float cn = stepf(cl, u1, u2, ol, p);
        cl = (j >= gate_j) ? cn : cl;
    }

    // ---- core (buffers trajectory in smem) ----
    #pragma unroll 4
    for (int j = 0; j < L_C; j++) {
        ssc[lane * 65 + j] = cl;               // state ENTERING this step
        float u1 = u1n, u2 = u2n, ol = oln;
        int on = SWZ(base_o + WARM + j + 1);   // max SWZ(2112)=3201 < SU_SZ
        u1n = su1[on]; u2n = su2[on];
        oln = olgate(u2n, p);
        cl = stepf(cl, u1, u2, ol, p);
    }
    __syncwarp();

    // ---- coalesced drain ----
    for (int s = 0; s < 32; s++) {
        int ch = wch0 + s;
        if (ch >= nch) break;
        int cbase = tl + ch * L_C;
        #pragma unroll
        for (int e = lane; e < L_C; e += 32) {
            int gi = cbase + e;
            if (gi < n) g_c[gi] = ssc[s * 65 + e];
        }
    }
}

// ---------------------------------------------------------------------------
// Per-element gate computation for the epilogue (scalar form).
__device__ __forceinline__ void gates(float c0, float u2, const Par& sp,
                                      float& h, float& ol, float& olc,
                                      float& oo, float& f, float& ov) {
    ol = olgate(u2, sp);
    float t = fmaf(c0, sp.A2, sp.B2);
    float e;  asm("ex2.approx.f32 %0, %1;" : "=f"(e) : "f"(t));
    oo = sp.oo1 / (1.0f + e);
    if (c0 > 0.0f) olc = fminf(ol, u2 / c0); else olc = ol;
    f = (1.0f - oo) - olc;
    float s = fmaf(c0, 0.002f, sp.mthr);
    float sg = (s > 0.0f) ? sp.svm : ((s < 0.0f) ? sp.nsvm : 0.0f);
    ov = fminf(sg, f);
    h = oo * c0;
}

// Vectorized epilogue: 4 elements per thread, STG.128 per column.
// Layout: [h_n | c_n | l_n | lc_n | z | z | Goo | Gol | Golc | Gf |
//          h_nout(N,2 interleaved) | obs_std | Gov]
__global__ void k_out(const float2* __restrict__ x, int n,
                      const int* __restrict__ tlp, float* __restrict__ out,
                      const float* pm, const float* ps,
                      const float* wr_yom, const float* wr_ylm,
                      const float* wr_yfm, const float* wr_yvm,
                      const float* b0_yom, const float* wb1p,
                      const float* b0_ylm, const float* wb2p,
                      const float* b0_yrm) {
    __shared__ Par sp;
    __shared__ float sobs;
    if (threadIdx.x == 0) {
        sp = make_par(pm, ps, wr_yom, wr_ylm, wr_yfm, wr_yvm,
                      b0_yom, wb1p, b0_ylm, wb2p, b0_yrm);
        sobs = g_obs[0];
    }
    __syncthreads();

    int i0 = (blockIdx.x * blockDim.x + threadIdx.x) * 4;
    if (i0 >= n) return;
    int tl = tlp[0];
    if (tl < 0) tl = 0;
    long long nn = n;
    float obss = sobs;
    bool vec = ((n & 3) == 0) && (i0 + 4 <= n);

    if (vec && (i0 + 3) < tl) {
        float4 z = make_float4(0.f, 0.f, 0.f, 0.f);
        #pragma unroll
        for (int col = 0; col < 10; col++)
            *(float4*)(out + col*nn + i0) = z;
        *(float4*)(out + 10*nn + 2*(long long)i0)     = z;
        *(float4*)(out + 10*nn + 2*(long long)i0 + 4) = z;
        *(float4*)(out + 12*nn + i0) = z;
        *(float4*)(out + 13*nn + i0) = z;
        return;
    }

    if (vec && i0 >= tl) {
        float4 c4  = *(const float4*)(g_c + i0);
        float4 x01 = __ldg((const float4*)(x + i0));
        float4 x23 = __ldg((const float4*)(x + i0) + 1);
        float c0a[4] = {c4.x, c4.y, c4.z, c4.w};
        float u2a[4] = {x01.y, x01.w, x23.y, x23.w};
        float h[4], ol[4], olc[4], oo[4], f[4], ov[4];
        #pragma unroll
        for (int j = 0; j < 4; j++)
            gates(c0a[j], u2a[j], sp, h[j], ol[j], olc[j], oo[j], f[j], ov[j]);

        float4 z = make_float4(0.f, 0.f, 0.f, 0.f);
        *(float4*)(out + i0)        = make_float4(h[0], h[1], h[2], h[3]);
        *(float4*)(out + nn + i0)   = c4;
        *(float4*)(out + 2*nn + i0) = make_float4(ol[0]*c0a[0], ol[1]*c0a[1],
                                                  ol[2]*c0a[2], ol[3]*c0a[3]);
        *(float4*)(out + 3*nn + i0) = make_float4(olc[0]*c0a[0], olc[1]*c0a[1],
                                                  olc[2]*c0a[2], olc[3]*c0a[3]);
        *(float4*)(out + 4*nn + i0) = z;
        *(float4*)(out + 5*nn + i0) = z;
        *(float4*)(out + 6*nn + i0) = make_float4(oo[0], oo[1], oo[2], oo[3]);
        *(float4*)(out + 7*nn + i0) = make_float4(ol[0], ol[1], ol[2], ol[3]);
        *(float4*)(out + 8*nn + i0) = make_float4(olc[0], olc[1], olc[2], olc[3]);
        *(float4*)(out + 9*nn + i0) = make_float4(f[0], f[1], f[2], f[3]);
        *(float4*)(out + 10*nn + 2*(long long)i0)
            = make_float4(h[0], obss, h[1], obss);
        *(float4*)(out + 10*nn + 2*(long long)i0 + 4)
            = make_float4(h[2], obss, h[3], obss);
        *(float4*)(out + 12*nn + i0) = make_float4(obss, obss, obss, obss);
        *(float4*)(out + 13*nn + i0) = make_float4(ov[0], ov[1], ov[2], ov[3]);
        return;
    }

    // scalar fallback (straddle / tail)
    for (int j = 0; j < 4; j++) {
        int i = i0 + j;
        if (i >= n) break;
        if (i < tl) {
            out[i] = 0.0f;            out[nn + i] = 0.0f;
            out[2*nn + i] = 0.0f;     out[3*nn + i] = 0.0f;
            out[4*nn + i] = 0.0f;     out[5*nn + i] = 0.0f;
            out[6*nn + i] = 0.0f;     out[7*nn + i] = 0.0f;
            out[8*nn + i] = 0.0f;     out[9*nn + i] = 0.0f;
            out[10*nn + 2*(long long)i]     = 0.0f;
            out[10*nn + 2*(long long)i + 1] = 0.0f;
            out[12*nn + i] = 0.0f;    out[13*nn + i] = 0.0f;
            continue;
        }
        float c0 = g_c[i];
        float u2 = x[i].y;
        float h, ol, olc, oo, f, ov;
        gates(c0, u2, sp, h, ol, olc, oo, f, ov);
        out[i]         = h;
        out[nn + i]    = c0;
        out[2*nn + i]  = ol * c0;
        out[3*nn + i]  = olc * c0;
        out[4*nn + i]  = 0.0f;
        out[5*nn + i]  = 0.0f;
        out[6*nn + i]  = oo;
        out[7*nn + i]  = ol;
        out[8*nn + i]  = olc;
        out[9*nn + i]  = f;
        out[10*nn + 2*(long long)i]     = h;
        out[10*nn + 2*(long long)i + 1] = obss;
        out[12*nn + i] = obss;
        out[13*nn + i] = ov;
    }
}

// ---------------------------------------------------------------------------
extern "C" void kernel_launch(void* const* d_in, const int* in_sizes, int n_in,
                              void* d_out, int out_size) {
    const float2* x   = (const float2*)d_in[0];
    const float*  y   = (const float*)d_in[1];
    const float*  pm  = (const float*)d_in[2];
    const float*  ps  = (const float*)d_in[3];
    const float*  wr_yom = (const float*)d_in[4];
    const float*  wr_ylm = (const float*)d_in[5];
    const float*  wr_yfm = (const float*)d_in[6];
    const float*  wr_yvm = (const float*)d_in[7];
    const float*  b0_yom = (const float*)d_in[8];
    const float*  wb1    = (const float*)d_in[9];
    const float*  b0_ylm = (const float*)d_in[10];
    const float*  wb2    = (const float*)d_in[11];
    const float*  b0_yrm = (const float*)d_in[12];
    const int*    tlp    = (const int*)d_in[14];   // time_lag
    float* out = (float*)d_out;
    (void)n_in; (void)out_size;

    int n  = in_sizes[0] / 2;
    if (n > MAXN) n = MAXN;
    int ny = in_sizes[1];

    cudaFuncSetAttribute(k_main, cudaFuncAttributeMaxDynamicSharedMemorySize,
                         SCAN_SMEM);

    k_main<<<TOT_BLOCKS, SCAN_TPB, SCAN_SMEM>>>(x, n, tlp, y, ny,
        pm, ps, wr_yom, wr_ylm, wr_yfm, wr_yvm,
        b0_yom, wb1, b0_ylm, wb2, b0_yrm);
    int groups = (n + 3) / 4;
    k_out<<<(groups + 255) / 256, 256>>>(x, n, tlp, out,
        pm, ps, wr_yom, wr_ylm, wr_yfm, wr_yvm,
        b0_yom, wb1, b0_ylm, wb2, b0_yrm);
}

// round 11
// speedup vs baseline: 1740.1021x; 1.0013x over previous
#include <cuda_runtime.h>
#include <math.h>

// Problem constants (from reference)
#define MAXN   524288
#define SPIN   1000
#define TRAINN 400000
#define ML_C   2.9086f
#define SL_C   1.898f

#define L_C    64                 // core steps per chunk (lane)
#define WARM   64                 // speculative burn-in (contraction)
#define STEPS  (WARM + L_C)       // 128 sequential steps per lane
#define SPAN   (31*L_C + STEPS)   // 2112 unique elements per warp
#define SU_SZ  3208               // >= SWZ(SPAN)=3201 (+pad)
#define SWZ(o) ((o) + 33*((o) >> 6))
#define SCAN_TPB 64
#define SCAN_BLOCKS 128
#define REDB2   64                // reduce blocks appended to the scan grid
#define TOT_BLOCKS (SCAN_BLOCKS + REDB2)
// smem: su1,su2 (2 warps x 2 x SU_SZ) + 3 state arrays (2 warps x 65*32)
#define SCAN_SMEM ((4*SU_SZ + 2*3*65*32) * 4)

// Scratch (no allocations allowed)
__device__ double   g_part[REDB2*2];  // per-block partial sums
__device__ unsigned g_ctr = 0;        // completion counter (self-resetting)
__device__ float    g_obs[1];         // obsstd result

// ---------------------------------------------------------------------------
struct Par {
    float A2, B2, oo1, noo1, svm, nsvm, mthr, K, AL, BL, ol1;
};

__device__ __forceinline__ Par make_par(
        const float* pm, const float* ps,
        const float* wr_yom, const float* wr_ylm,
        const float* wr_yfm, const float* wr_yvm,
        const float* b0_yom, const float* wb1p,
        const float* b0_ylm, const float* wb2p,
        const float* b0_yrm) {
    const float LOG2E = 1.4426950408889634f;
    Par p;
    float eo = expf(wr_yom[0]);
    float el = expf(wr_ylm[0]);
    float ef = expf(wr_yfm[0]);
    float den = eo + el + ef;
    p.oo1  = eo / den;
    p.ol1  = el / den;
    p.noo1 = -p.oo1;
    p.svm  = 1.0f / (1.0f + expf(-wr_yvm[0]));
    p.nsvm = -p.svm;
    float thr = expf(b0_yrm[0]);
    p.mthr = -thr;
    p.K    = thr * 500.0f;
    float a = wb1p[0] / ps[0];
    p.A2 = -LOG2E * a;
    p.B2 = -LOG2E * (b0_yom[0] - pm[0] * a);
    float al = wb2p[0] / SL_C;
    p.AL = -LOG2E * al;
    p.BL = -LOG2E * (b0_ylm[0] - ML_C * al);
    return p;
}

__device__ __forceinline__ float olgate(float u2, const Par& p) {
    float t = fmaf(u2, p.AL, p.BL);
    float e; asm("ex2.approx.f32 %0, %1;" : "=f"(e) : "f"(t));
    float r; asm("rcp.approx.f32 %0, %1;" : "=f"(r) : "f"(1.0f + e));
    return p.ol1 * r;
}

// ---------------------------------------------------------------------------
// Fused kernel.
// Blocks [0, SCAN_BLOCKS): warp-SIMD speculative chunk scan. Each warp owns
// 32 consecutive chunks (lane = chunk). The warp's input span is staged once
// (coalesced, swizzled). WARM burn-in from c=0 (contraction |dc1/dc0| << 1
// makes the speculative state converge below fp32 resolution; chunk 0 is
// exactly gated). Core steps store (c0, r, ol) per element to smem; the
// drain derives ALL gates from them (no ex2, one rcp) and writes the 9
// state-dependent output columns directly — there is no separate epilogue
// kernel and no g_c round trip.
// Blocks [SCAN_BLOCKS, TOT_BLOCKS): concurrent fp32 obsstd reduction.
__global__ void __launch_bounds__(SCAN_TPB, 1)
k_main(const float2* __restrict__ x, int n, const int* __restrict__ tlp,
       float* __restrict__ out,
       const float* __restrict__ y, int ny,
       const float* pm, const float* ps,
       const float* wr_yom, const float* wr_ylm,
       const float* wr_yfm, const float* wr_yvm,
       const float* b0_yom, const float* wb1p,
       const float* b0_ylm, const float* wb2p,
       const float* b0_yrm) {
    extern __shared__ float smem[];

    if (blockIdx.x >= SCAN_BLOCKS) {
        // ---------------- obsstd reduction (fp32 accumulate) ----------------
        __shared__ double rsh[2][2];
        __shared__ int    lastf;
        int rb  = blockIdx.x - SCAN_BLOCKS;
        int tid = threadIdx.x;
        int hi = TRAINN < ny ? TRAINN : ny;
        int count = hi - SPIN;
        float s = 0.0f, s2 = 0.0f;
        for (int i = rb * SCAN_TPB + tid; i < count; i += REDB2 * SCAN_TPB) {
            float v = y[SPIN + i];
            s += v;
            s2 = fmaf(v, v, s2);
        }
        #pragma unroll
        for (int o = 16; o; o >>= 1) {
            s  += __shfl_down_sync(0xFFFFFFFFu, s,  o);
            s2 += __shfl_down_sync(0xFFFFFFFFu, s2, o);
        }
        int w = tid >> 5;
        if ((tid & 31) == 0) { rsh[w][0] = (double)s; rsh[w][1] = (double)s2; }
        __syncthreads();
        if (tid == 0) {
            g_part[2*rb]     = rsh[0][0] + rsh[1][0];
            g_part[2*rb + 1] = rsh[0][1] + rsh[1][1];
            __threadfence();
            unsigned t = atomicAdd(&g_ctr, 1u);
            lastf = (t == REDB2 - 1) ? 1 : 0;
        }
        __syncthreads();
        if (lastf) {
            double ds = 0.0, ds2 = 0.0;
            if (tid < REDB2) { ds = g_part[2*tid]; ds2 = g_part[2*tid + 1]; }
            #pragma unroll
            for (int o = 16; o; o >>= 1) {
                ds  += __shfl_down_sync(0xFFFFFFFFu, ds,  o);
                ds2 += __shfl_down_sync(0xFFFFFFFFu, ds2, o);
            }
            if ((tid & 31) == 0) { rsh[tid >> 5][0] = ds; rsh[tid >> 5][1] = ds2; }
            __syncthreads();
            if (tid == 0) {
                double ts  = rsh[0][0] + rsh[1][0];
                double ts2 = rsh[0][1] + rsh[1][1];
                double cnt = (double)count;
                float res = 0.0f;
                if (count > 1) {
                    double var = (ts2 - ts * ts / cnt) / (cnt - 1.0);
                    res = (float)sqrt(var > 0.0 ? var : 0.0);
                }
                g_obs[0] = res;
                g_ctr = 0;            // reset for next graph replay
            }
        }
        return;
    }

    // ------------------------------ scan ------------------------------
    int wid  = threadIdx.x >> 5;
    int lane = threadIdx.x & 31;
    float* su1  = smem + wid * SU_SZ;
    float* su2  = smem + 2 * SU_SZ + wid * SU_SZ;
    float* s_c0 = smem + 4 * SU_SZ + wid * (3 * 65 * 32);
    float* s_r  = s_c0 + 65 * 32;
    float* s_ol = s_r  + 65 * 32;

    int tl = tlp[0];
    if (tl < 0) tl = 0;
    if (tl > n) tl = n;
    int nrem = n - tl;
    if (nrem <= 0) return;
    int nch = (nrem + L_C - 1) / L_C;

    int wch0 = (blockIdx.x * 2 + wid) * 32;   // warp's first chunk
    if (wch0 >= nch) return;

    Par p = make_par(pm, ps, wr_yom, wr_ylm, wr_yfm, wr_yvm,
                     b0_yom, wb1p, b0_ylm, wb2p, b0_yrm);

    int spanbase = tl + wch0 * L_C - WARM;

    // ---- single-shot coalesced staging of the warp's span ----
    #pragma unroll 8
    for (int o = lane; o < SPAN; o += 32) {
        int idx = spanbase + o;
        idx = idx < 0 ? 0 : (idx >= n ? n - 1 : idx);
        float2 v = x[idx];
        int so = SWZ(o);
        su1[so] = v.x;
        su2[so] = v.y;
    }
    __syncwarp();

    int gate_j = WARM - (wch0 + lane) * L_C;  // update admitted iff j >= gate_j
    int base_o = lane * L_C;

    float cl = 0.0f;
    int o0 = SWZ(base_o);
    float u1n = su1[o0], u2n = su2[o0];
    float oln = olgate(u2n, p);

    // ---- warm-up (discarded; gated so chunk 0 is exact) ----
    #pragma unroll 4
    for (int j = 0; j < WARM; j++) {
        float u1 = u1n, u2 = u2n, ol = oln;
        int on = SWZ(base_o + j + 1);
        u1n = su1[on]; u2n = su2[on];
        oln = olgate(u2n, p);

        float c0 = cl;
        float t = fmaf(c0, p.A2, p.B2);
        float e;  asm("ex2.approx.f32 %0, %1;" : "=f"(e) : "f"(t));
        float d = 1.0f + e;
        float r;  asm("rcp.approx.f32 %0, %1;" : "=f"(r) : "f"(d));
        float rc; asm("rcp.approx.f32 %0, %1;" : "=f"(rc) : "f"(c0));
        bool  pos  = c0 > 0.0f;
        float absd = fabsf(c0 - p.K);
        float olc0 = ol * c0;
        float mn   = fminf(olc0, u2);
        float mlc  = pos ? mn : olc0;
        float Bv   = (c0 + u1) - mlc;
        float s    = fmaf(c0, 0.002f, p.mthr);
        float sgp  = (s > 0.0f) ? p.svm : 0.0f;
        float sg   = (s < 0.0f) ? p.nsvm : sgp;
        float C1   = fmaf(-sg, absd, Bv);
        float k1   = p.noo1 * c0;
        float qa   = u2 * absd;
        float qr   = qa * rc;
        float ola  = ol * absd;
        float oabm = fminf(ola, qr);
        float oab  = pos ? oabm : ola;
        float k2   = p.oo1 * (absd - c0);
        float C2   = (Bv - absd) + oab;
        float cn   = fmaxf(fmaf(k1, r, C1), fmaf(k2, r, C2));
        cl = (j >= gate_j) ? cn : cl;
    }

    // ---- core: run steps, record (c0, r, ol) per element ----
    #pragma unroll 4
    for (int j = 0; j < L_C; j++) {
        float u1 = u1n, u2 = u2n, ol = oln;
        int on = SWZ(base_o + WARM + j + 1);   // max SWZ(2112)=3201 < SU_SZ
        u1n = su1[on]; u2n = su2[on];
        oln = olgate(u2n, p);

        float c0 = cl;
        float t = fmaf(c0, p.A2, p.B2);
        float e;  asm("ex2.approx.f32 %0, %1;" : "=f"(e) : "f"(t));
        float d = 1.0f + e;
        float r;  asm("rcp.approx.f32 %0, %1;" : "=f"(r) : "f"(d));
        float rc; asm("rcp.approx.f32 %0, %1;" : "=f"(rc) : "f"(c0));

        s_c0[lane * 65 + j] = c0;              // state ENTERING this step
        s_r [lane * 65 + j] = r;
        s_ol[lane * 65 + j] = ol;

        bool  pos  = c0 > 0.0f;
        float absd = fabsf(c0 - p.K);
        float olc0 = ol * c0;
        float mn   = fminf(olc0, u2);
        float mlc  = pos ? mn : olc0;
        float Bv   = (c0 + u1) - mlc;
        float s    = fmaf(c0, 0.002f, p.mthr);
        float sgp  = (s > 0.0f) ? p.svm : 0.0f;
        float sg   = (s < 0.0f) ? p.nsvm : sgp;
        float C1   = fmaf(-sg, absd, Bv);
        float k1   = p.noo1 * c0;
        float qa   = u2 * absd;
        float qr   = qa * rc;
        float ola  = ol * absd;
        float oabm = fminf(ola, qr);
        float oab  = pos ? oabm : ola;
        float k2   = p.oo1 * (absd - c0);
        float C2   = (Bv - absd) + oab;
        cl = fmaxf(fmaf(k1, r, C1), fmaf(k2, r, C2));
    }
    __syncwarp();

    // ---- drain: derive gates from (c0, r, ol, u2) and write 9 columns ----
    long long nn = n;
    for (int s = 0; s < 32; s++) {
        int ch = wch0 + s;
        if (ch >= nch) break;
        int cbase = tl + ch * L_C;
        #pragma unroll
        for (int e = lane; e < L_C; e += 32) {
            int gi = cbase + e;
            if (gi >= n) continue;
            float c0 = s_c0[s * 65 + e];
            float r  = s_r [s * 65 + e];
            float ol = s_ol[s * 65 + e];
            float u2 = su2[SWZ(s * L_C + WARM + e)];
            float rc; asm("rcp.approx.f32 %0, %1;" : "=f"(rc) : "f"(c0));
            float oo  = p.oo1 * r;
            float q   = u2 * rc;
            float olc = (c0 > 0.0f) ? fminf(ol, q) : ol;
            float f   = (1.0f - oo) - olc;
            float sx  = fmaf(c0, 0.002f, p.mthr);
            float sg  = (sx > 0.0f) ? p.svm : ((sx < 0.0f) ? p.nsvm : 0.0f);
            float ov  = fminf(sg, f);
            float h   = oo * c0;
            out[gi]          = h;
            out[nn + gi]     = c0;
            out[2*nn + gi]   = ol * c0;
            out[3*nn + gi]   = olc * c0;
            out[6*nn + gi]   = oo;
            out[7*nn + gi]   = ol;
            out[8*nn + gi]   = olc;
            out[9*nn + gi]   = f;
            out[13*nn + gi]  = ov;
        }
    }
}

// ---------------------------------------------------------------------------
// Streaming fill: zero columns 4,5, obss column 12, h_nout pairs (col 10,
// reading h back from column 0), and the full zero prefix for i < tl.
__global__ void k_fill(int n, const int* __restrict__ tlp,
                       float* __restrict__ out) {
    int i0 = (blockIdx.x * blockDim.x + threadIdx.x) * 4;
    if (i0 >= n) return;
    int tl = tlp[0];
    if (tl < 0) tl = 0;
    long long nn = n;
    float ob = g_obs[0];
    bool vec = ((n & 3) == 0) && (i0 + 4 <= n);

    if (vec && i0 >= tl) {
        float4 h4 = *(const float4*)(out + i0);
        float4 z  = make_float4(0.f, 0.f, 0.f, 0.f);
        *(float4*)(out + 4*nn + i0) = z;
        *(float4*)(out + 5*nn + i0) = z;
        *(float4*)(out + 10*nn + 2*(long long)i0)
            = make_float4(h4.x, ob, h4.y, ob);
        *(float4*)(out + 10*nn + 2*(long long)i0 + 4)
            = make_float4(h4.z, ob, h4.w, ob);
        *(float4*)(out + 12*nn + i0) = make_float4(ob, ob, ob, ob);
        return;
    }
    if (vec && (i0 + 3) < tl) {
        float4 z = make_float4(0.f, 0.f, 0.f, 0.f);
        #pragma unroll
        for (int col = 0; col < 10; col++)
            *(float4*)(out + col*nn + i0) = z;
        *(float4*)(out + 10*nn + 2*(long long)i0)     = z;
        *(float4*)(out + 10*nn + 2*(long long)i0 + 4) = z;
        *(float4*)(out + 12*nn + i0) = z;
        *(float4*)(out + 13*nn + i0) = z;
        return;
    }
    // scalar straddle / tail
    for (int j = 0; j < 4; j++) {
        int i = i0 + j;
        if (i >= n) break;
        if (i < tl) {
            out[i] = 0.0f;            out[nn + i] = 0.0f;
            out[2*nn + i] = 0.0f;     out[3*nn + i] = 0.0f;
            out[4*nn + i] = 0.0f;     out[5*nn + i] = 0.0f;
            out[6*nn + i] = 0.0f;     out[7*nn + i] = 0.0f;
            out[8*nn + i] = 0.0f;     out[9*nn + i] = 0.0f;
            out[10*nn + 2*(long long)i]     = 0.0f;
            out[10*nn + 2*(long long)i + 1] = 0.0f;
            out[12*nn + i] = 0.0f;    out[13*nn + i] = 0.0f;
        } else {
            float h = out[i];
            out[4*nn + i] = 0.0f;
            out[5*nn + i] = 0.0f;
            out[10*nn + 2*(long long)i]     = h;
            out[10*nn + 2*(long long)i + 1] = ob;
            out[12*nn + i] = ob;
        }
    }
}

// ---------------------------------------------------------------------------
extern "C" void kernel_launch(void* const* d_in, const int* in_sizes, int n_in,
                              void* d_out, int out_size) {
    const float2* x   = (const float2*)d_in[0];
    const float*  y   = (const float*)d_in[1];
    const float*  pm  = (const float*)d_in[2];
    const float*  ps  = (const float*)d_in[3];
    const float*  wr_yom = (const float*)d_in[4];
    const float*  wr_ylm = (const float*)d_in[5];
    const float*  wr_yfm = (const float*)d_in[6];
    const float*  wr_yvm = (const float*)d_in[7];
    const float*  b0_yom = (const float*)d_in[8];
    const float*  wb1    = (const float*)d_in[9];
    const float*  b0_ylm = (const float*)d_in[10];
    const float*  wb2    = (const float*)d_in[11];
    const float*  b0_yrm = (const float*)d_in[12];
    const int*    tlp    = (const int*)d_in[14];   // time_lag
    float* out = (float*)d_out;
    (void)n_in; (void)out_size;

    int n  = in_sizes[0] / 2;
    if (n > MAXN) n = MAXN;
    int ny = in_sizes[1];

    cudaFuncSetAttribute(k_main, cudaFuncAttributeMaxDynamicSharedMemorySize,
                         SCAN_SMEM);

    k_main<<<TOT_BLOCKS, SCAN_TPB, SCAN_SMEM>>>(x, n, tlp, out, y, ny,
        pm, ps, wr_yom, wr_ylm, wr_yfm, wr_yvm,
        b0_yom, wb1, b0_ylm, wb2, b0_yrm);
    int groups = (n + 3) / 4;
    k_fill<<<(groups + 255) / 256, 256>>>(n, tlp, out);
}